// round 6
// baseline (speedup 1.0000x reference)
#include <cuda_runtime.h>
#include <cuda_bf16.h>
#include <cstdint>

// Problem constants
#define BB   512
#define TT   64
#define CC   512
#define HH   512
#define NCLS 96
#define NS   26

// ---------------- device scratch -------------------------------------------
__device__ float g_Hproj[(size_t)BB * TT * HH];
__device__ float g_q   [(size_t)BB * HH];
__device__ float g_ctx [(size_t)BB * HH];
__device__ float g_hA  [(size_t)BB * HH];     // h double buffer (race fix)
__device__ float g_hB  [(size_t)BB * HH];
__device__ float g_c   [(size_t)BB * HH];
__device__ float g_hs  [(size_t)BB * NS * HH];
__device__ float g_lkP [(size_t)(CC + NCLS) * 4 * HH];   // permuted lstm_kernel
__device__ float g_lrP [(size_t)HH * 4 * HH];            // permuted lstm_rec
__device__ float g_lbP [(size_t)4 * HH];                 // permuted lstm_bias

// ---------------- tf32 helpers ----------------------------------------------
__device__ __forceinline__ float to_tf32(float x) {
    uint32_t r;
    asm("cvt.rna.tf32.f32 %0, %1;" : "=r"(r) : "f"(x));
    return __uint_as_float(r);
}
__device__ __forceinline__ void mma_tf32(float* d, const uint32_t* a, const uint32_t* b) {
    asm volatile(
        "mma.sync.aligned.m16n8k8.row.col.f32.tf32.tf32.f32 "
        "{%0,%1,%2,%3}, {%4,%5,%6,%7}, {%8,%9}, {%0,%1,%2,%3};"
        : "+f"(d[0]), "+f"(d[1]), "+f"(d[2]), "+f"(d[3])
        : "r"(a[0]), "r"(a[1]), "r"(a[2]), "r"(a[3]),
          "r"(b[0]), "r"(b[1]));
}
__device__ __forceinline__ float sigm(float x) { return 1.f / (1.f + __expf(-x)); }

// ---------------- warp-MMA tf32 GEMM, fragment-order smem -------------------
// Block tile 64x64, BK=32, 128 threads (4 warps, warp tile 32x32), ping-pong.
// MODE 0: C = A1@B1 (+A2@B2) (+bias).
// MODE 1: fused LSTM gates epilogue; C = h_out buffer.
#define BM 64
#define BN 64
#define BK 32

#define AF_IDX(buf,kb8,mb,lane) (((((buf)*4+(kb8))*4+(mb))*32 + (lane))*4)
#define BF_IDX(buf,kb8,nb,lane) (4096 + ((((buf)*4+(kb8))*8+(nb))*32 + (lane))*2)

template<int MODE>
__global__ __launch_bounds__(128)
void gemm_mma2(const float* __restrict__ A1, const float* __restrict__ B1,
               const float* __restrict__ A2, const float* __restrict__ B2,
               const float* __restrict__ bias, float* __restrict__ C,
               int M, int N, int K, int lda, int ldb, int ldc,
               const float* __restrict__ lkP, const float* __restrict__ lbP,
               const int* __restrict__ text, int step)
{
    __shared__ alignas(16) float SM[8192];

    const int tid = threadIdx.x;
    const int wid = tid >> 5, lane = tid & 31;
    const int warpM = wid >> 1, warpN = wid & 1;
    const int g = lane >> 2, t = lane & 3;
    const int m0 = blockIdx.y * BM, n0 = blockIdx.x * BN;

    const int kpt = K / BK;
    const int npass = (A2 != nullptr) ? 2 : 1;
    const int nk = kpt * npass;

    float acc[2][4][4];
#pragma unroll
    for (int i = 0; i < 2; ++i)
#pragma unroll
        for (int j = 0; j < 4; ++j)
#pragma unroll
            for (int k = 0; k < 4; ++k) acc[i][j][k] = 0.f;

    auto fetch = [&](int kt, float4* rA, float4* rB) {
        const int pass = kt / kpt;
        const int k0 = (kt - pass * kpt) * BK;
        const float* __restrict__ A = pass ? A2 : A1;
        const float* __restrict__ B = pass ? B2 : B1;
#pragma unroll
        for (int i = 0; i < 4; ++i) {
            int l = tid + 128 * i;
            int row = l >> 3, q = l & 7;
            rA[i] = *(const float4*)(A + (size_t)(m0 + row) * lda + k0 + q * 4);
        }
#pragma unroll
        for (int i = 0; i < 4; ++i) {
            int l = tid + 128 * i;
            int k = l >> 4, q = l & 15;
            int n = n0 + q * 4;
            if (n + 3 < N) {
                rB[i] = *(const float4*)(B + (size_t)(k0 + k) * ldb + n);
            } else {
                float4 v = make_float4(0.f, 0.f, 0.f, 0.f);
                const float* src = B + (size_t)(k0 + k) * ldb;
                float* vf = (float*)&v;
#pragma unroll
                for (int e = 0; e < 4; ++e)
                    if (n + e < N) vf[e] = src[n + e];
                rB[i] = v;
            }
        }
    };
    auto stage = [&](const float4* rA, const float4* rB, int buf) {
#pragma unroll
        for (int i = 0; i < 4; ++i) {
            int l = tid + 128 * i;
            int row = l >> 3, q = l & 7;
            const float* vf = (const float*)&rA[i];
            int base = AF_IDX(buf, q >> 1, row >> 4, (row & 7) * 4);
            int reg = ((row >> 3) & 1) + 2 * (q & 1);
#pragma unroll
            for (int e = 0; e < 4; ++e)
                SM[base + e * 4 + reg] = to_tf32(vf[e]);
        }
#pragma unroll
        for (int i = 0; i < 4; ++i) {
            int l = tid + 128 * i;
            int k = l >> 4, q = l & 15;
            const float* vf = (const float*)&rB[i];
            int kb8 = k >> 3;
            int lane0 = ((q & 1) * 4) * 4 + (k & 3);
            int base = BF_IDX(buf, kb8, q >> 1, 0) + lane0 * 2 + ((k >> 2) & 1);
#pragma unroll
            for (int e = 0; e < 4; ++e)
                SM[base + e * 8] = to_tf32(vf[e]);
        }
    };

    {
        float4 rA[4], rB[4];
        fetch(0, rA, rB);
        stage(rA, rB, 0);
    }
    __syncthreads();

    for (int kt = 0; kt < nk; ++kt) {
        const int buf = kt & 1;
        const bool more = (kt + 1 < nk);
        float4 rA[4], rB[4];
        if (more) fetch(kt + 1, rA, rB);

#pragma unroll
        for (int kb8 = 0; kb8 < 4; ++kb8) {
            float4 a4[2];
            float2 b2[4];
#pragma unroll
            for (int mt = 0; mt < 2; ++mt)
                a4[mt] = *(const float4*)&SM[AF_IDX(buf, kb8, warpM * 2 + mt, lane)];
#pragma unroll
            for (int nt = 0; nt < 4; ++nt)
                b2[nt] = *(const float2*)&SM[BF_IDX(buf, kb8, warpN * 4 + nt, lane)];
#pragma unroll
            for (int mt = 0; mt < 2; ++mt)
#pragma unroll
                for (int nt = 0; nt < 4; ++nt)
                    mma_tf32(acc[mt][nt], (const uint32_t*)&a4[mt], (const uint32_t*)&b2[nt]);
        }

        if (more) stage(rA, rB, buf ^ 1);
        __syncthreads();
    }

    if (MODE == 0) {
#pragma unroll
        for (int mt = 0; mt < 2; ++mt) {
#pragma unroll
            for (int nt = 0; nt < 4; ++nt) {
                const int col = n0 + warpN * 32 + nt * 8 + 2 * t;
                const int row = m0 + warpM * 32 + mt * 16 + g;
                float b0 = 0.f, b1 = 0.f;
                if (bias && col < N) b0 = bias[col];
                if (bias && col + 1 < N) b1 = bias[col + 1];
                if (col + 1 < N) {
                    *(float2*)(C + (size_t)row * ldc + col) =
                        make_float2(acc[mt][nt][0] + b0, acc[mt][nt][1] + b1);
                    *(float2*)(C + (size_t)(row + 8) * ldc + col) =
                        make_float2(acc[mt][nt][2] + b0, acc[mt][nt][3] + b1);
                } else if (col < N) {
                    C[(size_t)row * ldc + col]       = acc[mt][nt][0] + b0;
                    C[(size_t)(row + 8) * ldc + col] = acc[mt][nt][2] + b0;
                }
            }
        }
    } else {
        // fused LSTM gates epilogue; C = h_out (double buffer, race-free).
        float* zs = SM;
        const int PITCH = 66;
#pragma unroll
        for (int mt = 0; mt < 2; ++mt) {
#pragma unroll
            for (int nt = 0; nt < 4; ++nt) {
                const int c0 = warpN * 32 + nt * 8 + 2 * t;
                const int r0 = warpM * 32 + mt * 16 + g;
                zs[r0 * PITCH + c0]           = acc[mt][nt][0];
                zs[r0 * PITCH + c0 + 1]       = acc[mt][nt][1];
                zs[(r0 + 8) * PITCH + c0]     = acc[mt][nt][2];
                zs[(r0 + 8) * PITCH + c0 + 1] = acc[mt][nt][3];
            }
        }
        __syncthreads();
        const int j0 = n0 >> 2;
#pragma unroll
        for (int p = tid; p < 64 * 16; p += 128) {
            const int r = p & 63, jj = p >> 6;
            const int b = m0 + r, j = j0 + jj;
            const int ch = text[b * NS + step];
            const float* zrow = zs + r * PITCH + jj * 4;
            float4 oh = *(const float4*)(lkP + (size_t)(CC + ch) * (4 * HH) + 4 * j);
            float4 bb = *(const float4*)(lbP + 4 * j);
            float zi = zrow[0] + oh.x + bb.x;
            float zf = zrow[1] + oh.y + bb.y;
            float zg = zrow[2] + oh.z + bb.z;
            float zo = zrow[3] + oh.w + bb.w;
            const int ci = b * HH + j;
            float cn = sigm(zf) * g_c[ci] + sigm(zi) * tanhf(zg);
            float hn = sigm(zo) * tanhf(cn);
            g_c[ci] = cn;
            C[ci] = hn;                                   // h_out
            g_hs[((size_t)b * NS + step) * HH + j] = hn;
        }
    }
}

// ---------------- gate-interleave permutation: out[row][4j+g] = in[row][g*512+j]
__global__ __launch_bounds__(256)
void permute_gates(const float* __restrict__ in, float* __restrict__ out, int total)
{
    int idx = blockIdx.x * 256 + threadIdx.x;
    if (idx >= total) return;
    int row = idx >> 11, oc = idx & 2047;
    int j = oc >> 2, gate = oc & 3;
    out[idx] = in[(size_t)row * 2048 + gate * HH + j];
}

// ---------------- fused attention --------------------------------------------
__global__ __launch_bounds__(256)
void attn_kernel(const float* __restrict__ q,
                 const float* __restrict__ batch_H,
                 const float* __restrict__ Ws,
                 float* __restrict__ ctx)
{
    const int b = blockIdx.x;
    __shared__ float qs[HH];
    __shared__ float ws[HH];
    __shared__ float e[TT];

    const int tid = threadIdx.x;
    for (int i = tid; i < HH; i += 256) { qs[i] = q[(size_t)b * HH + i]; ws[i] = Ws[i]; }
    __syncthreads();

    const int warp = tid >> 5, lane = tid & 31;
    for (int t = warp; t < TT; t += 8) {
        const float* __restrict__ hp = g_Hproj + ((size_t)b * TT + t) * HH;
        float p = 0.f;
#pragma unroll 4
        for (int h = lane; h < HH; h += 32)
            p += tanhf(hp[h] + qs[h]) * ws[h];
#pragma unroll
        for (int o = 16; o; o >>= 1) p += __shfl_xor_sync(0xffffffffu, p, o);
        if (lane == 0) e[t] = p;
    }
    __syncthreads();

    if (warp == 0) {
        float v0 = e[lane], v1 = e[lane + 32];
        float m = fmaxf(v0, v1);
#pragma unroll
        for (int o = 16; o; o >>= 1) m = fmaxf(m, __shfl_xor_sync(0xffffffffu, m, o));
        float x0 = __expf(v0 - m), x1 = __expf(v1 - m);
        float s = x0 + x1;
#pragma unroll
        for (int o = 16; o; o >>= 1) s += __shfl_xor_sync(0xffffffffu, s, o);
        float inv = 1.f / s;
        e[lane] = x0 * inv;
        e[lane + 32] = x1 * inv;
    }
    __syncthreads();

    for (int c = tid; c < CC; c += 256) {
        const float* __restrict__ bhp = batch_H + (size_t)b * TT * CC + c;
        float acc = 0.f;
#pragma unroll 8
        for (int t = 0; t < TT; ++t)
            acc = fmaf(e[t], bhp[(size_t)t * CC], acc);
        ctx[(size_t)b * CC + c] = acc;
    }
}

// ---------------- launch -----------------------------------------------------
extern "C" void kernel_launch(void* const* d_in, const int* in_sizes, int n_in,
                              void* d_out, int out_size)
{
    int off = 0;
    if (n_in >= 3 && in_sizes[2] == 1) off = 1;
    const float* batch_H = (const float*)d_in[0];
    const int*   text    = (const int*)  d_in[1];
    const float* Wi      = (const float*)d_in[2 + off];
    const float* Wh      = (const float*)d_in[3 + off];
    const float* bh      = (const float*)d_in[4 + off];
    const float* Ws      = (const float*)d_in[5 + off];
    const float* lk      = (const float*)d_in[6 + off];
    const float* lr      = (const float*)d_in[7 + off];
    const float* lb      = (const float*)d_in[8 + off];
    const float* Wgen    = (const float*)d_in[9 + off];
    const float* bgen    = (const float*)d_in[10 + off];

    float *Hproj, *q, *ctx, *hA, *hB, *c, *hs, *lkP, *lrP, *lbP;
    cudaGetSymbolAddress((void**)&Hproj, g_Hproj);
    cudaGetSymbolAddress((void**)&q,     g_q);
    cudaGetSymbolAddress((void**)&ctx,   g_ctx);
    cudaGetSymbolAddress((void**)&hA,    g_hA);
    cudaGetSymbolAddress((void**)&hB,    g_hB);
    cudaGetSymbolAddress((void**)&c,     g_c);
    cudaGetSymbolAddress((void**)&hs,    g_hs);
    cudaGetSymbolAddress((void**)&lkP,   g_lkP);
    cudaGetSymbolAddress((void**)&lrP,   g_lrP);
    cudaGetSymbolAddress((void**)&lbP,   g_lbP);

    cudaMemsetAsync(hA, 0, (size_t)BB * HH * sizeof(float));
    cudaMemsetAsync(c,  0, (size_t)BB * HH * sizeof(float));

    // permute gate weights: [.., gate*512+j] -> [.., 4j+gate]
    permute_gates<<<((CC + NCLS) * 4 * HH + 255) / 256, 256>>>(lk, lkP, (CC + NCLS) * 4 * HH);
    permute_gates<<<(HH * 4 * HH + 255) / 256, 256>>>(lr, lrP, HH * 4 * HH);
    permute_gates<<<(4 * HH + 255) / 256, 256>>>(lb, lbP, 4 * HH);

    // Hproj = batch_H [B*T, C] @ Wi [C, H]
    gemm_mma2<0><<<dim3(HH / BN, (BB * TT) / BM), 128>>>(
        batch_H, Wi, nullptr, nullptr, nullptr, Hproj,
        BB * TT, HH, CC, CC, HH, HH, nullptr, nullptr, nullptr, 0);

    float* hbuf[2] = { hA, hB };
    for (int s = 0; s < NS; ++s) {
        float* hin  = hbuf[s & 1];
        float* hout = hbuf[(s + 1) & 1];
        // q = h_in @ Wh + bh
        gemm_mma2<0><<<dim3(HH / BN, BB / BM), 128>>>(
            hin, Wh, nullptr, nullptr, bh, q,
            BB, HH, HH, HH, HH, HH, nullptr, nullptr, nullptr, 0);
        attn_kernel<<<BB, 256>>>(q, batch_H, Ws, ctx);
        // fused: z = ctx @ lkP[0:512] + h_in @ lrP ; gates -> h_out, c, hs
        gemm_mma2<1><<<dim3((4 * HH) / BN, BB / BM), 128>>>(
            ctx, lkP, hin, lrP, nullptr, hout,
            BB, 4 * HH, CC, CC, 4 * HH, 4 * HH, lkP, lbP, text, s);
    }

    // probs = hs [B*NS, H] @ Wgen [H, NC] + bgen
    gemm_mma2<0><<<dim3((NCLS + BN - 1) / BN, (BB * NS) / BM), 128>>>(
        hs, Wgen, nullptr, nullptr, bgen, (float*)d_out,
        BB * NS, NCLS, HH, HH, NCLS, NCLS, nullptr, nullptr, nullptr, 0);
}

// round 7
// speedup vs baseline: 1.2626x; 1.2626x over previous
#include <cuda_runtime.h>
#include <cuda_bf16.h>
#include <cstdint>

// Problem constants
#define BB   512
#define TT   64
#define CC   512
#define HH   512
#define NCLS 96
#define NS   26

// ---------------- device scratch -------------------------------------------
__device__ float g_Hproj[(size_t)BB * TT * HH];
__device__ float g_q   [(size_t)BB * HH];
__device__ float g_ctx [(size_t)BB * HH];
__device__ float g_hA  [(size_t)BB * HH];     // h double buffer
__device__ float g_hB  [(size_t)BB * HH];
__device__ float g_c   [(size_t)BB * HH];
__device__ float g_hs  [(size_t)BB * NS * HH];
__device__ float g_lkP [(size_t)(CC + NCLS) * 4 * HH];
__device__ float g_lrP [(size_t)HH * 4 * HH];
__device__ float g_lbP [(size_t)4 * HH];

// ---------------- tf32 helpers ----------------------------------------------
__device__ __forceinline__ float to_tf32(float x) {
    uint32_t r;
    asm("cvt.rna.tf32.f32 %0, %1;" : "=r"(r) : "f"(x));
    return __uint_as_float(r);
}
__device__ __forceinline__ void mma_tf32(float* d, const uint32_t* a, const uint32_t* b) {
    asm volatile(
        "mma.sync.aligned.m16n8k8.row.col.f32.tf32.tf32.f32 "
        "{%0,%1,%2,%3}, {%4,%5,%6,%7}, {%8,%9}, {%0,%1,%2,%3};"
        : "+f"(d[0]), "+f"(d[1]), "+f"(d[2]), "+f"(d[3])
        : "r"(a[0]), "r"(a[1]), "r"(a[2]), "r"(a[3]),
          "r"(b[0]), "r"(b[1]));
}
__device__ __forceinline__ float sigm(float x) { return 1.f / (1.f + __expf(-x)); }

// ---------------- warp-MMA tf32 GEMM, fragment-order smem -------------------
// Block tile 64x64, BK=32, 128 threads (4 warps, warp tile 32x32), ping-pong.
// Staging assignment = fragment slot ownership -> conflict-free STS.128/STS.64.
#define BM 64
#define BN 64
#define BK 32

// AF[buf][kb8][mb][lane][reg0..3] ; BF[buf][kb8][nb][lane][reg0..1]
#define AF_IDX(buf,kb8,mb,lane) (((((buf)*4+(kb8))*4+(mb))*32 + (lane))*4)
#define BF_IDX(buf,kb8,nb,lane) (4096 + ((((buf)*4+(kb8))*8+(nb))*32 + (lane))*2)

template<int MODE>
__global__ __launch_bounds__(128)
void gemm_mma2(const float* __restrict__ A1, const float* __restrict__ B1,
               const float* __restrict__ A2, const float* __restrict__ B2,
               const float* __restrict__ bias, float* __restrict__ C,
               int M, int N, int K, int lda, int ldb, int ldc,
               const float* __restrict__ lkP, const float* __restrict__ lbP,
               const int* __restrict__ text, int step)
{
    __shared__ alignas(16) float SM[8192];

    const int tid = threadIdx.x;
    const int wid = tid >> 5, lane = tid & 31;
    const int warpM = wid >> 1, warpN = wid & 1;
    const int g = lane >> 2, t = lane & 3;
    const int m0 = blockIdx.y * BM, n0 = blockIdx.x * BN;

    const int kpt = K / BK;
    const int npass = (A2 != nullptr) ? 2 : 1;
    const int nk = kpt * npass;

    float acc[2][4][4];
#pragma unroll
    for (int i = 0; i < 2; ++i)
#pragma unroll
        for (int j = 0; j < 4; ++j)
#pragma unroll
            for (int k = 0; k < 4; ++k) acc[i][j][k] = 0.f;

    // A slots: thread owns (kb8=i, mb=(tid>>5)&3, lane) for i in 0..3
    const int a_mb = (tid >> 5) & 3;
    // B slots: thread owns slot = i*128+tid -> nb=(i*4+(tid>>5))&7, kb8=(i*4+(tid>>5))>>3
    // Per-slot fetch: A -> 4 scalars forming fragment regs, B -> 2 scalars.
    auto fetch = [&](int kt, float4* rA, float2* rB) {
        const int pass = kt / kpt;
        const int k0 = (kt - pass * kpt) * BK;
        const float* __restrict__ A = pass ? A2 : A1;
        const float* __restrict__ B = pass ? B2 : B1;
#pragma unroll
        for (int i = 0; i < 4; ++i) {           // kb8 = i
            const float* src = A + (size_t)(m0 + a_mb * 16 + g) * lda + k0 + i * 8 + t;
            rA[i].x = src[0];                   // (m+0, k+0)
            rA[i].y = src[(size_t)8 * lda];     // (m+8, k+0)
            rA[i].z = src[4];                   // (m+0, k+4)
            rA[i].w = src[(size_t)8 * lda + 4]; // (m+8, k+4)
        }
#pragma unroll
        for (int i = 0; i < 8; ++i) {
            const int sl = i * 4 + (tid >> 5);
            const int nb = sl & 7, kb8 = sl >> 3;
            const int n = n0 + nb * 8 + g;
            const int k = k0 + kb8 * 8 + t;
            float v0 = 0.f, v1 = 0.f;
            if (n < N) {
                v0 = B[(size_t)k * ldb + n];
                v1 = B[(size_t)(k + 4) * ldb + n];
            }
            rB[i] = make_float2(v0, v1);
        }
    };
    auto stage = [&](const float4* rA, const float2* rB, int buf) {
#pragma unroll
        for (int i = 0; i < 4; ++i) {
            float4 v;
            v.x = to_tf32(rA[i].x); v.y = to_tf32(rA[i].y);
            v.z = to_tf32(rA[i].z); v.w = to_tf32(rA[i].w);
            *(float4*)&SM[AF_IDX(buf, i, a_mb, lane)] = v;
        }
#pragma unroll
        for (int i = 0; i < 8; ++i) {
            const int sl = i * 4 + (tid >> 5);
            const int nb = sl & 7, kb8 = sl >> 3;
            float2 v = make_float2(to_tf32(rB[i].x), to_tf32(rB[i].y));
            *(float2*)&SM[BF_IDX(buf, kb8, nb, lane)] = v;
        }
    };

    {
        float4 rA[4]; float2 rB[8];
        fetch(0, rA, rB);
        stage(rA, rB, 0);
    }
    __syncthreads();

    for (int kt = 0; kt < nk; ++kt) {
        const int buf = kt & 1;
        const bool more = (kt + 1 < nk);
        float4 rA[4]; float2 rB[8];
        if (more) fetch(kt + 1, rA, rB);

#pragma unroll
        for (int kb8 = 0; kb8 < 4; ++kb8) {
            float4 a4[2];
            float2 b2[4];
#pragma unroll
            for (int mt = 0; mt < 2; ++mt)
                a4[mt] = *(const float4*)&SM[AF_IDX(buf, kb8, warpM * 2 + mt, lane)];
#pragma unroll
            for (int nt = 0; nt < 4; ++nt)
                b2[nt] = *(const float2*)&SM[BF_IDX(buf, kb8, warpN * 4 + nt, lane)];
#pragma unroll
            for (int mt = 0; mt < 2; ++mt)
#pragma unroll
                for (int nt = 0; nt < 4; ++nt)
                    mma_tf32(acc[mt][nt], (const uint32_t*)&a4[mt], (const uint32_t*)&b2[nt]);
        }

        if (more) stage(rA, rB, buf ^ 1);
        __syncthreads();
    }

    if (MODE == 0) {
#pragma unroll
        for (int mt = 0; mt < 2; ++mt) {
#pragma unroll
            for (int nt = 0; nt < 4; ++nt) {
                const int col = n0 + warpN * 32 + nt * 8 + 2 * t;
                const int row = m0 + warpM * 32 + mt * 16 + g;
                float b0 = 0.f, b1 = 0.f;
                if (bias && col < N) b0 = bias[col];
                if (bias && col + 1 < N) b1 = bias[col + 1];
                if (col + 1 < N) {
                    *(float2*)(C + (size_t)row * ldc + col) =
                        make_float2(acc[mt][nt][0] + b0, acc[mt][nt][1] + b1);
                    *(float2*)(C + (size_t)(row + 8) * ldc + col) =
                        make_float2(acc[mt][nt][2] + b0, acc[mt][nt][3] + b1);
                } else if (col < N) {
                    C[(size_t)row * ldc + col]       = acc[mt][nt][0] + b0;
                    C[(size_t)(row + 8) * ldc + col] = acc[mt][nt][2] + b0;
                }
            }
        }
    } else {
        // fused LSTM gates epilogue; C = h_out (double buffer, race-free).
        float* zs = SM;
        const int PITCH = 66;
#pragma unroll
        for (int mt = 0; mt < 2; ++mt) {
#pragma unroll
            for (int nt = 0; nt < 4; ++nt) {
                const int c0 = warpN * 32 + nt * 8 + 2 * t;
                const int r0 = warpM * 32 + mt * 16 + g;
                zs[r0 * PITCH + c0]           = acc[mt][nt][0];
                zs[r0 * PITCH + c0 + 1]       = acc[mt][nt][1];
                zs[(r0 + 8) * PITCH + c0]     = acc[mt][nt][2];
                zs[(r0 + 8) * PITCH + c0 + 1] = acc[mt][nt][3];
            }
        }
        __syncthreads();
        const int j0 = n0 >> 2;
#pragma unroll
        for (int p = tid; p < 64 * 16; p += 128) {
            const int r = p & 63, jj = p >> 6;
            const int b = m0 + r, j = j0 + jj;
            const int ch = text[b * NS + step];
            const float* zrow = zs + r * PITCH + jj * 4;
            float4 oh = *(const float4*)(lkP + (size_t)(CC + ch) * (4 * HH) + 4 * j);
            float4 bb = *(const float4*)(lbP + 4 * j);
            float zi = zrow[0] + oh.x + bb.x;
            float zf = zrow[1] + oh.y + bb.y;
            float zg = zrow[2] + oh.z + bb.z;
            float zo = zrow[3] + oh.w + bb.w;
            const int ci = b * HH + j;
            float cn = sigm(zf) * g_c[ci] + sigm(zi) * tanhf(zg);
            float hn = sigm(zo) * tanhf(cn);
            g_c[ci] = cn;
            C[ci] = hn;
            g_hs[((size_t)b * NS + step) * HH + j] = hn;
        }
    }
}

// ---------------- gate-interleave permutation --------------------------------
__global__ __launch_bounds__(256)
void permute_gates(const float* __restrict__ in, float* __restrict__ out, int total)
{
    int idx = blockIdx.x * 256 + threadIdx.x;
    if (idx >= total) return;
    int row = idx >> 11, oc = idx & 2047;
    int j = oc >> 2, gate = oc & 3;
    out[idx] = in[(size_t)row * 2048 + gate * HH + j];
}

// ---------------- fused attention --------------------------------------------
__global__ __launch_bounds__(256)
void attn_kernel(const float* __restrict__ q,
                 const float* __restrict__ batch_H,
                 const float* __restrict__ Ws,
                 float* __restrict__ ctx)
{
    const int b = blockIdx.x;
    __shared__ float qs[HH];
    __shared__ float ws[HH];
    __shared__ float e[TT];

    const int tid = threadIdx.x;
    for (int i = tid; i < HH; i += 256) { qs[i] = q[(size_t)b * HH + i]; ws[i] = Ws[i]; }
    __syncthreads();

    const int warp = tid >> 5, lane = tid & 31;
    for (int t = warp; t < TT; t += 8) {
        const float* __restrict__ hp = g_Hproj + ((size_t)b * TT + t) * HH;
        float p = 0.f;
#pragma unroll 4
        for (int h = lane; h < HH; h += 32)
            p += tanhf(hp[h] + qs[h]) * ws[h];
#pragma unroll
        for (int o = 16; o; o >>= 1) p += __shfl_xor_sync(0xffffffffu, p, o);
        if (lane == 0) e[t] = p;
    }
    __syncthreads();

    if (warp == 0) {
        float v0 = e[lane], v1 = e[lane + 32];
        float m = fmaxf(v0, v1);
#pragma unroll
        for (int o = 16; o; o >>= 1) m = fmaxf(m, __shfl_xor_sync(0xffffffffu, m, o));
        float x0 = __expf(v0 - m), x1 = __expf(v1 - m);
        float s = x0 + x1;
#pragma unroll
        for (int o = 16; o; o >>= 1) s += __shfl_xor_sync(0xffffffffu, s, o);
        float inv = 1.f / s;
        e[lane] = x0 * inv;
        e[lane + 32] = x1 * inv;
    }
    __syncthreads();

    for (int c = tid; c < CC; c += 256) {
        const float* __restrict__ bhp = batch_H + (size_t)b * TT * CC + c;
        float acc = 0.f;
#pragma unroll 8
        for (int t = 0; t < TT; ++t)
            acc = fmaf(e[t], bhp[(size_t)t * CC], acc);
        ctx[(size_t)b * CC + c] = acc;
    }
}

// ---------------- launch -----------------------------------------------------
extern "C" void kernel_launch(void* const* d_in, const int* in_sizes, int n_in,
                              void* d_out, int out_size)
{
    int off = 0;
    if (n_in >= 3 && in_sizes[2] == 1) off = 1;
    const float* batch_H = (const float*)d_in[0];
    const int*   text    = (const int*)  d_in[1];
    const float* Wi      = (const float*)d_in[2 + off];
    const float* Wh      = (const float*)d_in[3 + off];
    const float* bh      = (const float*)d_in[4 + off];
    const float* Ws      = (const float*)d_in[5 + off];
    const float* lk      = (const float*)d_in[6 + off];
    const float* lr      = (const float*)d_in[7 + off];
    const float* lb      = (const float*)d_in[8 + off];
    const float* Wgen    = (const float*)d_in[9 + off];
    const float* bgen    = (const float*)d_in[10 + off];

    float *Hproj, *q, *ctx, *hA, *hB, *c, *hs, *lkP, *lrP, *lbP;
    cudaGetSymbolAddress((void**)&Hproj, g_Hproj);
    cudaGetSymbolAddress((void**)&q,     g_q);
    cudaGetSymbolAddress((void**)&ctx,   g_ctx);
    cudaGetSymbolAddress((void**)&hA,    g_hA);
    cudaGetSymbolAddress((void**)&hB,    g_hB);
    cudaGetSymbolAddress((void**)&c,     g_c);
    cudaGetSymbolAddress((void**)&hs,    g_hs);
    cudaGetSymbolAddress((void**)&lkP,   g_lkP);
    cudaGetSymbolAddress((void**)&lrP,   g_lrP);
    cudaGetSymbolAddress((void**)&lbP,   g_lbP);

    cudaMemsetAsync(hA, 0, (size_t)BB * HH * sizeof(float));
    cudaMemsetAsync(c,  0, (size_t)BB * HH * sizeof(float));

    permute_gates<<<((CC + NCLS) * 4 * HH + 255) / 256, 256>>>(lk, lkP, (CC + NCLS) * 4 * HH);
    permute_gates<<<(HH * 4 * HH + 255) / 256, 256>>>(lr, lrP, HH * 4 * HH);
    permute_gates<<<(4 * HH + 255) / 256, 256>>>(lb, lbP, 4 * HH);

    // Hproj = batch_H [B*T, C] @ Wi [C, H]
    gemm_mma2<0><<<dim3(HH / BN, (BB * TT) / BM), 128>>>(
        batch_H, Wi, nullptr, nullptr, nullptr, Hproj,
        BB * TT, HH, CC, CC, HH, HH, nullptr, nullptr, nullptr, 0);

    float* hbuf[2] = { hA, hB };
    for (int s = 0; s < NS; ++s) {
        float* hin  = hbuf[s & 1];
        float* hout = hbuf[(s + 1) & 1];
        gemm_mma2<0><<<dim3(HH / BN, BB / BM), 128>>>(
            hin, Wh, nullptr, nullptr, bh, q,
            BB, HH, HH, HH, HH, HH, nullptr, nullptr, nullptr, 0);
        attn_kernel<<<BB, 256>>>(q, batch_H, Ws, ctx);
        gemm_mma2<1><<<dim3((4 * HH) / BN, BB / BM), 128>>>(
            ctx, lkP, hin, lrP, nullptr, hout,
            BB, 4 * HH, CC, CC, 4 * HH, 4 * HH, lkP, lbP, text, s);
    }

    // probs = hs [B*NS, H] @ Wgen [H, NC] + bgen
    gemm_mma2<0><<<dim3((NCLS + BN - 1) / BN, (BB * NS) / BM), 128>>>(
        hs, Wgen, nullptr, nullptr, bgen, (float*)d_out,
        BB * NS, NCLS, HH, HH, NCLS, NCLS, nullptr, nullptr, nullptr, 0);
}

// round 8
// speedup vs baseline: 1.2635x; 1.0007x over previous
#include <cuda_runtime.h>
#include <cuda_bf16.h>
#include <cstdint>

// Problem constants
#define BB   512
#define TT   64
#define CC   512
#define HH   512
#define NCLS 96
#define NS   26

// ---------------- device scratch -------------------------------------------
__device__ float g_Hproj[(size_t)BB * TT * HH];
__device__ float g_q   [(size_t)BB * HH];
__device__ float g_ctx [(size_t)BB * HH];
__device__ float g_hA  [(size_t)BB * HH];     // h double buffer
__device__ float g_hB  [(size_t)BB * HH];
__device__ float g_c   [(size_t)BB * HH];
__device__ float g_hs  [(size_t)BB * NS * HH];
__device__ float g_lkP [(size_t)(CC + NCLS) * 4 * HH];
__device__ float g_lrP [(size_t)HH * 4 * HH];
__device__ float g_lbP [(size_t)4 * HH];

// ---------------- tf32 helpers ----------------------------------------------
__device__ __forceinline__ float to_tf32(float x) {
    uint32_t r;
    asm("cvt.rna.tf32.f32 %0, %1;" : "=r"(r) : "f"(x));
    return __uint_as_float(r);
}
__device__ __forceinline__ void mma_tf32(float* d, const uint32_t* a, const uint32_t* b) {
    asm volatile(
        "mma.sync.aligned.m16n8k8.row.col.f32.tf32.tf32.f32 "
        "{%0,%1,%2,%3}, {%4,%5,%6,%7}, {%8,%9}, {%0,%1,%2,%3};"
        : "+f"(d[0]), "+f"(d[1]), "+f"(d[2]), "+f"(d[3])
        : "r"(a[0]), "r"(a[1]), "r"(a[2]), "r"(a[3]),
          "r"(b[0]), "r"(b[1]));
}
__device__ __forceinline__ float sigm(float x) { return 1.f / (1.f + __expf(-x)); }

// ---------------- warp-MMA tf32 GEMM, fragment-order smem -------------------
// Block tile 64x64, BK=32, 128 threads (4 warps, warp tile 32x32), ping-pong.
// Staging assignment = fragment slot ownership -> conflict-free STS.128/STS.64.
#define BM 64
#define BN 64
#define BK 32

// AF[buf][kb8][mb][lane][reg0..3] ; BF[buf][kb8][nb][lane][reg0..1]
#define AF_IDX(buf,kb8,mb,lane) (((((buf)*4+(kb8))*4+(mb))*32 + (lane))*4)
#define BF_IDX(buf,kb8,nb,lane) (4096 + ((((buf)*4+(kb8))*8+(nb))*32 + (lane))*2)

template<int MODE>
__global__ __launch_bounds__(128)
void gemm_mma2(const float* __restrict__ A1, const float* __restrict__ B1,
               const float* __restrict__ A2, const float* __restrict__ B2,
               const float* __restrict__ bias, float* __restrict__ C,
               int M, int N, int K, int lda, int ldb, int ldc,
               const float* __restrict__ lkP, const float* __restrict__ lbP,
               const int* __restrict__ text, int step)
{
    __shared__ alignas(16) float SM[8192];

    const int tid = threadIdx.x;
    const int wid = tid >> 5, lane = tid & 31;
    const int warpM = wid >> 1, warpN = wid & 1;
    const int g = lane >> 2, t = lane & 3;
    const int m0 = blockIdx.y * BM, n0 = blockIdx.x * BN;

    const int kpt = K / BK;
    const int npass = (A2 != nullptr) ? 2 : 1;
    const int nk = kpt * npass;

    float acc[2][4][4];
#pragma unroll
    for (int i = 0; i < 2; ++i)
#pragma unroll
        for (int j = 0; j < 4; ++j)
#pragma unroll
            for (int k = 0; k < 4; ++k) acc[i][j][k] = 0.f;

    // A slots: thread owns (kb8=i, mb=(tid>>5)&3, lane) for i in 0..3
    const int a_mb = (tid >> 5) & 3;
    // B slots: thread owns slot = i*128+tid -> nb=(i*4+(tid>>5))&7, kb8=(i*4+(tid>>5))>>3
    // Per-slot fetch: A -> 4 scalars forming fragment regs, B -> 2 scalars.
    auto fetch = [&](int kt, float4* rA, float2* rB) {
        const int pass = kt / kpt;
        const int k0 = (kt - pass * kpt) * BK;
        const float* __restrict__ A = pass ? A2 : A1;
        const float* __restrict__ B = pass ? B2 : B1;
#pragma unroll
        for (int i = 0; i < 4; ++i) {           // kb8 = i
            const float* src = A + (size_t)(m0 + a_mb * 16 + g) * lda + k0 + i * 8 + t;
            rA[i].x = src[0];                   // (m+0, k+0)
            rA[i].y = src[(size_t)8 * lda];     // (m+8, k+0)
            rA[i].z = src[4];                   // (m+0, k+4)
            rA[i].w = src[(size_t)8 * lda + 4]; // (m+8, k+4)
        }
#pragma unroll
        for (int i = 0; i < 8; ++i) {
            const int sl = i * 4 + (tid >> 5);
            const int nb = sl & 7, kb8 = sl >> 3;
            const int n = n0 + nb * 8 + g;
            const int k = k0 + kb8 * 8 + t;
            float v0 = 0.f, v1 = 0.f;
            if (n < N) {
                v0 = B[(size_t)k * ldb + n];
                v1 = B[(size_t)(k + 4) * ldb + n];
            }
            rB[i] = make_float2(v0, v1);
        }
    };
    auto stage = [&](const float4* rA, const float2* rB, int buf) {
#pragma unroll
        for (int i = 0; i < 4; ++i) {
            float4 v;
            v.x = to_tf32(rA[i].x); v.y = to_tf32(rA[i].y);
            v.z = to_tf32(rA[i].z); v.w = to_tf32(rA[i].w);
            *(float4*)&SM[AF_IDX(buf, i, a_mb, lane)] = v;
        }
#pragma unroll
        for (int i = 0; i < 8; ++i) {
            const int sl = i * 4 + (tid >> 5);
            const int nb = sl & 7, kb8 = sl >> 3;
            float2 v = make_float2(to_tf32(rB[i].x), to_tf32(rB[i].y));
            *(float2*)&SM[BF_IDX(buf, kb8, nb, lane)] = v;
        }
    };

    {
        float4 rA[4]; float2 rB[8];
        fetch(0, rA, rB);
        stage(rA, rB, 0);
    }
    __syncthreads();

    for (int kt = 0; kt < nk; ++kt) {
        const int buf = kt & 1;
        const bool more = (kt + 1 < nk);
        float4 rA[4]; float2 rB[8];
        if (more) fetch(kt + 1, rA, rB);

#pragma unroll
        for (int kb8 = 0; kb8 < 4; ++kb8) {
            float4 a4[2];
            float2 b2[4];
#pragma unroll
            for (int mt = 0; mt < 2; ++mt)
                a4[mt] = *(const float4*)&SM[AF_IDX(buf, kb8, warpM * 2 + mt, lane)];
#pragma unroll
            for (int nt = 0; nt < 4; ++nt)
                b2[nt] = *(const float2*)&SM[BF_IDX(buf, kb8, warpN * 4 + nt, lane)];
#pragma unroll
            for (int mt = 0; mt < 2; ++mt)
#pragma unroll
                for (int nt = 0; nt < 4; ++nt)
                    mma_tf32(acc[mt][nt], (const uint32_t*)&a4[mt], (const uint32_t*)&b2[nt]);
        }

        if (more) stage(rA, rB, buf ^ 1);
        __syncthreads();
    }

    if (MODE == 0) {
#pragma unroll
        for (int mt = 0; mt < 2; ++mt) {
#pragma unroll
            for (int nt = 0; nt < 4; ++nt) {
                const int col = n0 + warpN * 32 + nt * 8 + 2 * t;
                const int row = m0 + warpM * 32 + mt * 16 + g;
                float b0 = 0.f, b1 = 0.f;
                if (bias && col < N) b0 = bias[col];
                if (bias && col + 1 < N) b1 = bias[col + 1];
                if (col + 1 < N) {
                    *(float2*)(C + (size_t)row * ldc + col) =
                        make_float2(acc[mt][nt][0] + b0, acc[mt][nt][1] + b1);
                    *(float2*)(C + (size_t)(row + 8) * ldc + col) =
                        make_float2(acc[mt][nt][2] + b0, acc[mt][nt][3] + b1);
                } else if (col < N) {
                    C[(size_t)row * ldc + col]       = acc[mt][nt][0] + b0;
                    C[(size_t)(row + 8) * ldc + col] = acc[mt][nt][2] + b0;
                }
            }
        }
    } else {
        // fused LSTM gates epilogue; C = h_out (double buffer, race-free).
        float* zs = SM;
        const int PITCH = 66;
#pragma unroll
        for (int mt = 0; mt < 2; ++mt) {
#pragma unroll
            for (int nt = 0; nt < 4; ++nt) {
                const int c0 = warpN * 32 + nt * 8 + 2 * t;
                const int r0 = warpM * 32 + mt * 16 + g;
                zs[r0 * PITCH + c0]           = acc[mt][nt][0];
                zs[r0 * PITCH + c0 + 1]       = acc[mt][nt][1];
                zs[(r0 + 8) * PITCH + c0]     = acc[mt][nt][2];
                zs[(r0 + 8) * PITCH + c0 + 1] = acc[mt][nt][3];
            }
        }
        __syncthreads();
        const int j0 = n0 >> 2;
#pragma unroll
        for (int p = tid; p < 64 * 16; p += 128) {
            const int r = p & 63, jj = p >> 6;
            const int b = m0 + r, j = j0 + jj;
            const int ch = text[b * NS + step];
            const float* zrow = zs + r * PITCH + jj * 4;
            float4 oh = *(const float4*)(lkP + (size_t)(CC + ch) * (4 * HH) + 4 * j);
            float4 bb = *(const float4*)(lbP + 4 * j);
            float zi = zrow[0] + oh.x + bb.x;
            float zf = zrow[1] + oh.y + bb.y;
            float zg = zrow[2] + oh.z + bb.z;
            float zo = zrow[3] + oh.w + bb.w;
            const int ci = b * HH + j;
            float cn = sigm(zf) * g_c[ci] + sigm(zi) * tanhf(zg);
            float hn = sigm(zo) * tanhf(cn);
            g_c[ci] = cn;
            C[ci] = hn;
            g_hs[((size_t)b * NS + step) * HH + j] = hn;
        }
    }
}

// ---------------- gate-interleave permutation --------------------------------
__global__ __launch_bounds__(256)
void permute_gates(const float* __restrict__ in, float* __restrict__ out, int total)
{
    int idx = blockIdx.x * 256 + threadIdx.x;
    if (idx >= total) return;
    int row = idx >> 11, oc = idx & 2047;
    int j = oc >> 2, gate = oc & 3;
    out[idx] = in[(size_t)row * 2048 + gate * HH + j];
}

// ---------------- fused attention --------------------------------------------
__global__ __launch_bounds__(256)
void attn_kernel(const float* __restrict__ q,
                 const float* __restrict__ batch_H,
                 const float* __restrict__ Ws,
                 float* __restrict__ ctx)
{
    const int b = blockIdx.x;
    __shared__ float qs[HH];
    __shared__ float ws[HH];
    __shared__ float e[TT];

    const int tid = threadIdx.x;
    for (int i = tid; i < HH; i += 256) { qs[i] = q[(size_t)b * HH + i]; ws[i] = Ws[i]; }
    __syncthreads();

    const int warp = tid >> 5, lane = tid & 31;
    for (int t = warp; t < TT; t += 8) {
        const float* __restrict__ hp = g_Hproj + ((size_t)b * TT + t) * HH;
        float p = 0.f;
#pragma unroll 4
        for (int h = lane; h < HH; h += 32)
            p += tanhf(hp[h] + qs[h]) * ws[h];
#pragma unroll
        for (int o = 16; o; o >>= 1) p += __shfl_xor_sync(0xffffffffu, p, o);
        if (lane == 0) e[t] = p;
    }
    __syncthreads();

    if (warp == 0) {
        float v0 = e[lane], v1 = e[lane + 32];
        float m = fmaxf(v0, v1);
#pragma unroll
        for (int o = 16; o; o >>= 1) m = fmaxf(m, __shfl_xor_sync(0xffffffffu, m, o));
        float x0 = __expf(v0 - m), x1 = __expf(v1 - m);
        float s = x0 + x1;
#pragma unroll
        for (int o = 16; o; o >>= 1) s += __shfl_xor_sync(0xffffffffu, s, o);
        float inv = 1.f / s;
        e[lane] = x0 * inv;
        e[lane + 32] = x1 * inv;
    }
    __syncthreads();

    for (int c = tid; c < CC; c += 256) {
        const float* __restrict__ bhp = batch_H + (size_t)b * TT * CC + c;
        float acc = 0.f;
#pragma unroll 8
        for (int t = 0; t < TT; ++t)
            acc = fmaf(e[t], bhp[(size_t)t * CC], acc);
        ctx[(size_t)b * CC + c] = acc;
    }
}

// ---------------- launch -----------------------------------------------------
extern "C" void kernel_launch(void* const* d_in, const int* in_sizes, int n_in,
                              void* d_out, int out_size)
{
    int off = 0;
    if (n_in >= 3 && in_sizes[2] == 1) off = 1;
    const float* batch_H = (const float*)d_in[0];
    const int*   text    = (const int*)  d_in[1];
    const float* Wi      = (const float*)d_in[2 + off];
    const float* Wh      = (const float*)d_in[3 + off];
    const float* bh      = (const float*)d_in[4 + off];
    const float* Ws      = (const float*)d_in[5 + off];
    const float* lk      = (const float*)d_in[6 + off];
    const float* lr      = (const float*)d_in[7 + off];
    const float* lb      = (const float*)d_in[8 + off];
    const float* Wgen    = (const float*)d_in[9 + off];
    const float* bgen    = (const float*)d_in[10 + off];

    float *Hproj, *q, *ctx, *hA, *hB, *c, *hs, *lkP, *lrP, *lbP;
    cudaGetSymbolAddress((void**)&Hproj, g_Hproj);
    cudaGetSymbolAddress((void**)&q,     g_q);
    cudaGetSymbolAddress((void**)&ctx,   g_ctx);
    cudaGetSymbolAddress((void**)&hA,    g_hA);
    cudaGetSymbolAddress((void**)&hB,    g_hB);
    cudaGetSymbolAddress((void**)&c,     g_c);
    cudaGetSymbolAddress((void**)&hs,    g_hs);
    cudaGetSymbolAddress((void**)&lkP,   g_lkP);
    cudaGetSymbolAddress((void**)&lrP,   g_lrP);
    cudaGetSymbolAddress((void**)&lbP,   g_lbP);

    cudaMemsetAsync(hA, 0, (size_t)BB * HH * sizeof(float));
    cudaMemsetAsync(c,  0, (size_t)BB * HH * sizeof(float));

    permute_gates<<<((CC + NCLS) * 4 * HH + 255) / 256, 256>>>(lk, lkP, (CC + NCLS) * 4 * HH);
    permute_gates<<<(HH * 4 * HH + 255) / 256, 256>>>(lr, lrP, HH * 4 * HH);
    permute_gates<<<(4 * HH + 255) / 256, 256>>>(lb, lbP, 4 * HH);

    // Hproj = batch_H [B*T, C] @ Wi [C, H]
    gemm_mma2<0><<<dim3(HH / BN, (BB * TT) / BM), 128>>>(
        batch_H, Wi, nullptr, nullptr, nullptr, Hproj,
        BB * TT, HH, CC, CC, HH, HH, nullptr, nullptr, nullptr, 0);

    float* hbuf[2] = { hA, hB };
    for (int s = 0; s < NS; ++s) {
        float* hin  = hbuf[s & 1];
        float* hout = hbuf[(s + 1) & 1];
        gemm_mma2<0><<<dim3(HH / BN, BB / BM), 128>>>(
            hin, Wh, nullptr, nullptr, bh, q,
            BB, HH, HH, HH, HH, HH, nullptr, nullptr, nullptr, 0);
        attn_kernel<<<BB, 256>>>(q, batch_H, Ws, ctx);
        gemm_mma2<1><<<dim3((4 * HH) / BN, BB / BM), 128>>>(
            ctx, lkP, hin, lrP, nullptr, hout,
            BB, 4 * HH, CC, CC, 4 * HH, 4 * HH, lkP, lbP, text, s);
    }

    // probs = hs [B*NS, H] @ Wgen [H, NC] + bgen
    gemm_mma2<0><<<dim3((NCLS + BN - 1) / BN, (BB * NS) / BM), 128>>>(
        hs, Wgen, nullptr, nullptr, bgen, (float*)d_out,
        BB * NS, NCLS, HH, HH, NCLS, NCLS, nullptr, nullptr, nullptr, 0);
}

// round 9
// speedup vs baseline: 1.6403x; 1.2982x over previous
#include <cuda_runtime.h>
#include <cuda_bf16.h>
#include <cstdint>

// Problem constants
#define BB   512
#define TT   64
#define CC   512
#define HH   512
#define NCLS 96
#define NS   26

// ---------------- device scratch -------------------------------------------
__device__ float g_Hproj[(size_t)BB * TT * HH];
__device__ float g_bh32 [(size_t)BB * TT * CC];   // tf32-rounded batch_H
__device__ float g_q   [(size_t)BB * HH];
__device__ float g_ctx [(size_t)BB * HH];
__device__ float g_hA  [(size_t)BB * HH];
__device__ float g_hB  [(size_t)BB * HH];
__device__ float g_c   [(size_t)BB * HH];
__device__ float g_hs  [(size_t)BB * NS * HH];
__device__ float g_lkP [(size_t)(CC + NCLS) * 4 * HH];
__device__ float g_lrP [(size_t)HH * 4 * HH];
__device__ float g_lbP [(size_t)4 * HH];
__device__ float g_wi32[(size_t)CC * HH];
__device__ float g_wh32[(size_t)HH * HH];
__device__ float g_wg32[(size_t)HH * NCLS];

// ---------------- helpers ----------------------------------------------------
__device__ __forceinline__ float to_tf32(float x) {
    uint32_t r;
    asm("cvt.rna.tf32.f32 %0, %1;" : "=r"(r) : "f"(x));
    return __uint_as_float(r);
}
__device__ __forceinline__ void mma_tf32(float* d, const uint32_t* a, const uint32_t* b) {
    asm volatile(
        "mma.sync.aligned.m16n8k8.row.col.f32.tf32.tf32.f32 "
        "{%0,%1,%2,%3}, {%4,%5,%6,%7}, {%8,%9}, {%0,%1,%2,%3};"
        : "+f"(d[0]), "+f"(d[1]), "+f"(d[2]), "+f"(d[3])
        : "r"(a[0]), "r"(a[1]), "r"(a[2]), "r"(a[3]),
          "r"(b[0]), "r"(b[1]));
}
__device__ __forceinline__ float sigm(float x) { return 1.f / (1.f + __expf(-x)); }

// ---------------- cp.async 3-stage tf32 GEMM --------------------------------
// Block 64x64, BK=32, 128 threads (4 warps, warp tile 32x32).
// smem per stage: A[64][36] (9216B) + B[32][68] (8704B) = 17920B; 3 stages.
// All operands must be PRE-ROUNDED to tf32 (cp.async copies raw bits).
#define A_FLOATS     2304
#define B_FLOATS     2176
#define STAGE_FLOATS 4480
#define STAGE_BYTES  17920
#define SMEM_TOTAL   53760

template<int MODE>
__global__ __launch_bounds__(128)
void gemm_cp(const float* __restrict__ A1, const float* __restrict__ B1,
             const float* __restrict__ A2, const float* __restrict__ B2,
             const float* __restrict__ bias, float* __restrict__ C,
             int M, int N, int K, int lda, int ldb, int ldc,
             const float* __restrict__ lkP, const float* __restrict__ lbP,
             const int* __restrict__ text, int step)
{
    extern __shared__ float SM[];
    const int tid = threadIdx.x;
    const int wid = tid >> 5, lane = tid & 31;
    const int warpM = wid >> 1, warpN = wid & 1;
    const int g = lane >> 2, t = lane & 3;
    const int m0 = blockIdx.y * 64, n0 = blockIdx.x * 64;
    const int kpt = K / 32;
    const int npass = (A2 != nullptr) ? 2 : 1;
    const int nk = kpt * npass;
    const uint32_t sbase = (uint32_t)__cvta_generic_to_shared(SM);

    // pre-zero B slots that cp.async will skip (only when tile overhangs N)
    if (n0 + 64 > N) {
        for (int st = 0; st < 3; ++st)
            for (int i = tid; i < B_FLOATS; i += 128)
                SM[st * STAGE_FLOATS + A_FLOATS + i] = 0.f;
        __syncthreads();
    }

    float acc[2][4][4];
#pragma unroll
    for (int i = 0; i < 2; ++i)
#pragma unroll
        for (int j = 0; j < 4; ++j)
#pragma unroll
            for (int k = 0; k < 4; ++k) acc[i][j][k] = 0.f;

    auto issue = [&](int kt) {
        if (kt < nk) {
            const int pass = kt / kpt;
            const int k0 = (kt - pass * kpt) * 32;
            const float* __restrict__ A = pass ? A2 : A1;
            const float* __restrict__ B = pass ? B2 : B1;
            const uint32_t ab = sbase + (uint32_t)(kt % 3) * STAGE_BYTES;
            const uint32_t bb = ab + A_FLOATS * 4;
#pragma unroll
            for (int i = 0; i < 4; ++i) {
                const int lin = tid + 128 * i;
                const int row = lin >> 3, q = lin & 7;
                const uint32_t d = ab + (uint32_t)(row * 36 + q * 4) * 4u;
                const float* s = A + (size_t)(m0 + row) * lda + k0 + q * 4;
                asm volatile("cp.async.cg.shared.global [%0], [%1], 16;"
                             :: "r"(d), "l"(s));
            }
#pragma unroll
            for (int i = 0; i < 4; ++i) {
                const int lin = tid + 128 * i;
                const int kk = lin >> 4, q = lin & 15;
                const int n = n0 + q * 4;
                if (n + 3 < N) {
                    const uint32_t d = bb + (uint32_t)(kk * 68 + q * 4) * 4u;
                    const float* s = B + (size_t)(k0 + kk) * ldb + n;
                    asm volatile("cp.async.cg.shared.global [%0], [%1], 16;"
                                 :: "r"(d), "l"(s));
                }
            }
        }
        asm volatile("cp.async.commit_group;" ::: "memory");
    };

    issue(0);
    issue(1);

    for (int kt = 0; kt < nk; ++kt) {
        asm volatile("cp.async.wait_group 1;" ::: "memory");
        __syncthreads();
        issue(kt + 2);

        const float* __restrict__ As = SM + (kt % 3) * STAGE_FLOATS;
        const float* __restrict__ Bs = As + A_FLOATS;
#pragma unroll
        for (int kb8 = 0; kb8 < 4; ++kb8) {
            const int kk = kb8 * 8;
            uint32_t a[2][4], b[4][2];
#pragma unroll
            for (int mt = 0; mt < 2; ++mt) {
                const int m = warpM * 32 + mt * 16 + g;
                a[mt][0] = __float_as_uint(As[m * 36 + kk + t]);
                a[mt][1] = __float_as_uint(As[(m + 8) * 36 + kk + t]);
                a[mt][2] = __float_as_uint(As[m * 36 + kk + t + 4]);
                a[mt][3] = __float_as_uint(As[(m + 8) * 36 + kk + t + 4]);
            }
#pragma unroll
            for (int nt = 0; nt < 4; ++nt) {
                const int n = warpN * 32 + nt * 8 + g;
                b[nt][0] = __float_as_uint(Bs[(kk + t) * 68 + n]);
                b[nt][1] = __float_as_uint(Bs[(kk + t + 4) * 68 + n]);
            }
#pragma unroll
            for (int mt = 0; mt < 2; ++mt)
#pragma unroll
                for (int nt = 0; nt < 4; ++nt)
                    mma_tf32(acc[mt][nt], a[mt], b[nt]);
        }
    }

    if (MODE == 0) {
#pragma unroll
        for (int mt = 0; mt < 2; ++mt) {
#pragma unroll
            for (int nt = 0; nt < 4; ++nt) {
                const int col = n0 + warpN * 32 + nt * 8 + 2 * t;
                const int row = m0 + warpM * 32 + mt * 16 + g;
                float b0 = 0.f, b1 = 0.f;
                if (bias && col < N) b0 = bias[col];
                if (bias && col + 1 < N) b1 = bias[col + 1];
                if (col + 1 < N) {
                    *(float2*)(C + (size_t)row * ldc + col) =
                        make_float2(acc[mt][nt][0] + b0, acc[mt][nt][1] + b1);
                    *(float2*)(C + (size_t)(row + 8) * ldc + col) =
                        make_float2(acc[mt][nt][2] + b0, acc[mt][nt][3] + b1);
                } else if (col < N) {
                    C[(size_t)row * ldc + col]       = acc[mt][nt][0] + b0;
                    C[(size_t)(row + 8) * ldc + col] = acc[mt][nt][2] + b0;
                }
            }
        }
    } else {
        // fused LSTM gates; C = h_out (double-buffered). hs/h written tf32-rounded.
        __syncthreads();                 // all warps done reading fragments
        float* zs = SM;                  // [64][66]
        const int PITCH = 66;
#pragma unroll
        for (int mt = 0; mt < 2; ++mt) {
#pragma unroll
            for (int nt = 0; nt < 4; ++nt) {
                const int c0 = warpN * 32 + nt * 8 + 2 * t;
                const int r0 = warpM * 32 + mt * 16 + g;
                zs[r0 * PITCH + c0]           = acc[mt][nt][0];
                zs[r0 * PITCH + c0 + 1]       = acc[mt][nt][1];
                zs[(r0 + 8) * PITCH + c0]     = acc[mt][nt][2];
                zs[(r0 + 8) * PITCH + c0 + 1] = acc[mt][nt][3];
            }
        }
        __syncthreads();
        const int j0 = n0 >> 2;
#pragma unroll
        for (int p = tid; p < 64 * 16; p += 128) {
            const int r = p & 63, jj = p >> 6;
            const int b = m0 + r, j = j0 + jj;
            const int ch = text[b * NS + step];
            const float* zrow = zs + r * PITCH + jj * 4;
            float4 oh = *(const float4*)(lkP + (size_t)(CC + ch) * (4 * HH) + 4 * j);
            float4 bb = *(const float4*)(lbP + 4 * j);
            float zi = zrow[0] + oh.x + bb.x;
            float zf = zrow[1] + oh.y + bb.y;
            float zg = zrow[2] + oh.z + bb.z;
            float zo = zrow[3] + oh.w + bb.w;
            const int ci = b * HH + j;
            float cn = sigm(zf) * g_c[ci] + sigm(zi) * tanhf(zg);
            float hn = to_tf32(sigm(zo) * tanhf(cn));
            g_c[ci] = cn;
            C[ci] = hn;
            g_hs[((size_t)b * NS + step) * HH + j] = hn;
        }
    }
}

// ---------------- prep: gate-interleave permutation (+tf32 round) ------------
__global__ __launch_bounds__(256)
void permute_gates(const float* __restrict__ in, float* __restrict__ out, int total)
{
    int idx = blockIdx.x * 256 + threadIdx.x;
    if (idx >= total) return;
    int row = idx >> 11, oc = idx & 2047;
    int j = oc >> 2, gate = oc & 3;
    out[idx] = to_tf32(in[(size_t)row * 2048 + gate * HH + j]);
}

// ---------------- prep: tf32 round-copy (float4) ------------------------------
__global__ __launch_bounds__(256)
void round_copy(const float* __restrict__ in, float* __restrict__ out, int n4)
{
    int i = blockIdx.x * 256 + threadIdx.x;
    if (i >= n4) return;
    float4 v = ((const float4*)in)[i];
    v.x = to_tf32(v.x); v.y = to_tf32(v.y);
    v.z = to_tf32(v.z); v.w = to_tf32(v.w);
    ((float4*)out)[i] = v;
}

// ---------------- fused attention --------------------------------------------
__global__ __launch_bounds__(256)
void attn_kernel(const float* __restrict__ q,
                 const float* __restrict__ batch_H,
                 const float* __restrict__ Ws,
                 float* __restrict__ ctx)
{
    const int b = blockIdx.x;
    __shared__ float qs[HH];
    __shared__ float ws[HH];
    __shared__ float e[TT];

    const int tid = threadIdx.x;
    for (int i = tid; i < HH; i += 256) { qs[i] = q[(size_t)b * HH + i]; ws[i] = Ws[i]; }
    __syncthreads();

    const int warp = tid >> 5, lane = tid & 31;
    for (int t = warp; t < TT; t += 8) {
        const float* __restrict__ hp = g_Hproj + ((size_t)b * TT + t) * HH;
        float p = 0.f;
#pragma unroll 4
        for (int h = lane; h < HH; h += 32)
            p += tanhf(hp[h] + qs[h]) * ws[h];
#pragma unroll
        for (int o = 16; o; o >>= 1) p += __shfl_xor_sync(0xffffffffu, p, o);
        if (lane == 0) e[t] = p;
    }
    __syncthreads();

    if (warp == 0) {
        float v0 = e[lane], v1 = e[lane + 32];
        float m = fmaxf(v0, v1);
#pragma unroll
        for (int o = 16; o; o >>= 1) m = fmaxf(m, __shfl_xor_sync(0xffffffffu, m, o));
        float x0 = __expf(v0 - m), x1 = __expf(v1 - m);
        float s = x0 + x1;
#pragma unroll
        for (int o = 16; o; o >>= 1) s += __shfl_xor_sync(0xffffffffu, s, o);
        float inv = 1.f / s;
        e[lane] = x0 * inv;
        e[lane + 32] = x1 * inv;
    }
    __syncthreads();

    for (int c = tid; c < CC; c += 256) {
        const float* __restrict__ bhp = batch_H + (size_t)b * TT * CC + c;
        float acc = 0.f;
#pragma unroll 8
        for (int t = 0; t < TT; ++t)
            acc = fmaf(e[t], bhp[(size_t)t * CC], acc);
        ctx[(size_t)b * CC + c] = to_tf32(acc);   // ctx feeds GEMM: pre-round
    }
}

// ---------------- launch -----------------------------------------------------
extern "C" void kernel_launch(void* const* d_in, const int* in_sizes, int n_in,
                              void* d_out, int out_size)
{
    int off = 0;
    if (n_in >= 3 && in_sizes[2] == 1) off = 1;
    const float* batch_H = (const float*)d_in[0];
    const int*   text    = (const int*)  d_in[1];
    const float* Wi      = (const float*)d_in[2 + off];
    const float* Wh      = (const float*)d_in[3 + off];
    const float* bh      = (const float*)d_in[4 + off];
    const float* Ws      = (const float*)d_in[5 + off];
    const float* lk      = (const float*)d_in[6 + off];
    const float* lr      = (const float*)d_in[7 + off];
    const float* lb      = (const float*)d_in[8 + off];
    const float* Wgen    = (const float*)d_in[9 + off];
    const float* bgen    = (const float*)d_in[10 + off];

    float *Hproj, *bh32, *q, *ctx, *hA, *hB, *c, *hs, *lkP, *lrP, *lbP, *wi32, *wh32, *wg32;
    cudaGetSymbolAddress((void**)&Hproj, g_Hproj);
    cudaGetSymbolAddress((void**)&bh32,  g_bh32);
    cudaGetSymbolAddress((void**)&q,     g_q);
    cudaGetSymbolAddress((void**)&ctx,   g_ctx);
    cudaGetSymbolAddress((void**)&hA,    g_hA);
    cudaGetSymbolAddress((void**)&hB,    g_hB);
    cudaGetSymbolAddress((void**)&c,     g_c);
    cudaGetSymbolAddress((void**)&hs,    g_hs);
    cudaGetSymbolAddress((void**)&lkP,   g_lkP);
    cudaGetSymbolAddress((void**)&lrP,   g_lrP);
    cudaGetSymbolAddress((void**)&lbP,   g_lbP);
    cudaGetSymbolAddress((void**)&wi32,  g_wi32);
    cudaGetSymbolAddress((void**)&wh32,  g_wh32);
    cudaGetSymbolAddress((void**)&wg32,  g_wg32);

    static bool attr_done = false;
    if (!attr_done) {
        cudaFuncSetAttribute(gemm_cp<0>, cudaFuncAttributeMaxDynamicSharedMemorySize, SMEM_TOTAL);
        cudaFuncSetAttribute(gemm_cp<1>, cudaFuncAttributeMaxDynamicSharedMemorySize, SMEM_TOTAL);
        attr_done = true;
    }

    cudaMemsetAsync(hA, 0, (size_t)BB * HH * sizeof(float));
    cudaMemsetAsync(c,  0, (size_t)BB * HH * sizeof(float));

    // prep: permute + round gate weights; round-copy GEMM operands
    permute_gates<<<((CC + NCLS) * 4 * HH + 255) / 256, 256>>>(lk, lkP, (CC + NCLS) * 4 * HH);
    permute_gates<<<(HH * 4 * HH + 255) / 256, 256>>>(lr, lrP, HH * 4 * HH);
    permute_gates<<<(4 * HH + 255) / 256, 256>>>(lb, lbP, 4 * HH);
    round_copy<<<(BB * TT * CC / 4 + 255) / 256, 256>>>(batch_H, bh32, BB * TT * CC / 4);
    round_copy<<<(CC * HH / 4 + 255) / 256, 256>>>(Wi, wi32, CC * HH / 4);
    round_copy<<<(HH * HH / 4 + 255) / 256, 256>>>(Wh, wh32, HH * HH / 4);
    round_copy<<<(HH * NCLS / 4 + 255) / 256, 256>>>(Wgen, wg32, HH * NCLS / 4);

    // Hproj = bh32 [B*T, C] @ wi32 [C, H]
    gemm_cp<0><<<dim3(HH / 64, (BB * TT) / 64), 128, SMEM_TOTAL>>>(
        bh32, wi32, nullptr, nullptr, nullptr, Hproj,
        BB * TT, HH, CC, CC, HH, HH, nullptr, nullptr, nullptr, 0);

    float* hbuf[2] = { hA, hB };
    for (int s = 0; s < NS; ++s) {
        float* hin  = hbuf[s & 1];
        float* hout = hbuf[(s + 1) & 1];
        gemm_cp<0><<<dim3(HH / 64, BB / 64), 128, SMEM_TOTAL>>>(
            hin, wh32, nullptr, nullptr, bh, q,
            BB, HH, HH, HH, HH, HH, nullptr, nullptr, nullptr, 0);
        attn_kernel<<<BB, 256>>>(q, batch_H, Ws, ctx);
        gemm_cp<1><<<dim3((4 * HH) / 64, BB / 64), 128, SMEM_TOTAL>>>(
            ctx, lkP, hin, lrP, nullptr, hout,
            BB, 4 * HH, CC, CC, 4 * HH, 4 * HH, lkP, lbP, text, s);
    }

    // probs = hs [B*NS, H] @ wg32 [H, NC] + bgen
    gemm_cp<0><<<dim3((NCLS + 63) / 64, (BB * NS) / 64), 128, SMEM_TOTAL>>>(
        hs, wg32, nullptr, nullptr, bgen, (float*)d_out,
        BB * NS, NCLS, HH, HH, NCLS, NCLS, nullptr, nullptr, nullptr, 0);
}

// round 10
// speedup vs baseline: 1.7065x; 1.0404x over previous
#include <cuda_runtime.h>
#include <cuda_bf16.h>
#include <cstdint>

// Problem constants
#define BB   512
#define TT   64
#define CC   512
#define HH   512
#define NCLS 96
#define NS   26

// ---------------- device scratch -------------------------------------------
__device__ float g_Hproj[(size_t)BB * TT * HH];
__device__ float g_bh32 [(size_t)BB * TT * CC];
__device__ float g_q   [(size_t)BB * HH];
__device__ float g_ctx [(size_t)BB * HH];
__device__ float g_hA  [(size_t)BB * HH];
__device__ float g_hB  [(size_t)BB * HH];
__device__ float g_c   [(size_t)BB * HH];
__device__ float g_hs  [(size_t)BB * NS * HH];
__device__ float g_lkP [(size_t)(CC + NCLS) * 4 * HH];
__device__ float g_lrP [(size_t)HH * 4 * HH];
__device__ float g_lbP [(size_t)4 * HH];
__device__ float g_wi32[(size_t)CC * HH];
__device__ float g_wh32[(size_t)HH * HH];
__device__ float g_wg32[(size_t)HH * NCLS];

// ---------------- helpers ----------------------------------------------------
__device__ __forceinline__ float to_tf32(float x) {
    uint32_t r;
    asm("cvt.rna.tf32.f32 %0, %1;" : "=r"(r) : "f"(x));
    return __uint_as_float(r);
}
__device__ __forceinline__ void mma_tf32(float* d, const uint32_t* a, const uint32_t* b) {
    asm volatile(
        "mma.sync.aligned.m16n8k8.row.col.f32.tf32.tf32.f32 "
        "{%0,%1,%2,%3}, {%4,%5,%6,%7}, {%8,%9}, {%0,%1,%2,%3};"
        : "+f"(d[0]), "+f"(d[1]), "+f"(d[2]), "+f"(d[3])
        : "r"(a[0]), "r"(a[1]), "r"(a[2]), "r"(a[3]),
          "r"(b[0]), "r"(b[1]));
}
__device__ __forceinline__ float sigm(float x) { return 1.f / (1.f + __expf(-x)); }

// ---------------- cp.async 3-stage tf32 GEMM --------------------------------
// Block tile 64 x (NT*16), BK=32, 128 threads, 4 warps, warp tile 32 x (NT*8).
// NT=4 -> BN=64 (small-N GEMMs), NT=8 -> BN=128 (big GEMMs).
// A smem [64][36] (bank-perfect), B smem [32][BN+8] (bank-perfect frag loads).
// Operands must be pre-rounded to tf32.
#define A_FLOATS 2304

template<int MODE, int NT>
__global__ __launch_bounds__(128)
void gemm_cp(const float* __restrict__ A1, const float* __restrict__ B1,
             const float* __restrict__ A2, const float* __restrict__ B2,
             const float* __restrict__ bias, float* __restrict__ C,
             int M, int N, int K, int lda, int ldb, int ldc,
             const float* __restrict__ lkP, const float* __restrict__ lbP,
             const int* __restrict__ text, int step)
{
    constexpr int BN = NT * 16;
    constexpr int BPITCH = BN + 8;
    constexpr int B_FLOATS = 32 * BPITCH;
    constexpr int STAGE_FLOATS = A_FLOATS + B_FLOATS;
    constexpr int STAGE_BYTES = STAGE_FLOATS * 4;
    constexpr int BCHUNK = BN / 4;          // 16B chunks per B row

    extern __shared__ float SM[];
    const int tid = threadIdx.x;
    const int wid = tid >> 5, lane = tid & 31;
    const int warpM = wid >> 1, warpN = wid & 1;
    const int g = lane >> 2, t = lane & 3;
    const int m0 = blockIdx.y * 64, n0 = blockIdx.x * BN;
    const int kpt = K / 32;
    const int npass = (A2 != nullptr) ? 2 : 1;
    const int nk = kpt * npass;
    const uint32_t sbase = (uint32_t)__cvta_generic_to_shared(SM);

    if (n0 + BN > N) {
        for (int st = 0; st < 3; ++st)
            for (int i = tid; i < B_FLOATS; i += 128)
                SM[st * STAGE_FLOATS + A_FLOATS + i] = 0.f;
        __syncthreads();
    }

    float acc[2][NT][4];
#pragma unroll
    for (int i = 0; i < 2; ++i)
#pragma unroll
        for (int j = 0; j < NT; ++j)
#pragma unroll
            for (int k = 0; k < 4; ++k) acc[i][j][k] = 0.f;

    auto issue = [&](int kt) {
        if (kt < nk) {
            const int pass = kt / kpt;
            const int k0 = (kt - pass * kpt) * 32;
            const float* __restrict__ A = pass ? A2 : A1;
            const float* __restrict__ B = pass ? B2 : B1;
            const uint32_t ab = sbase + (uint32_t)(kt % 3) * STAGE_BYTES;
            const uint32_t bb = ab + A_FLOATS * 4;
#pragma unroll
            for (int i = 0; i < 4; ++i) {                 // A: 512 chunks
                const int lin = tid + 128 * i;
                const int row = lin >> 3, q = lin & 7;
                const uint32_t d = ab + (uint32_t)(row * 36 + q * 4) * 4u;
                const float* s = A + (size_t)(m0 + row) * lda + k0 + q * 4;
                asm volatile("cp.async.cg.shared.global [%0], [%1], 16;"
                             :: "r"(d), "l"(s));
            }
#pragma unroll
            for (int i = 0; i < NT; ++i) {                // B: 32*BCHUNK chunks
                const int lin = tid + 128 * i;
                const int kk = lin / BCHUNK, q = lin % BCHUNK;
                const int n = n0 + q * 4;
                if (n + 3 < N) {
                    const uint32_t d = bb + (uint32_t)(kk * BPITCH + q * 4) * 4u;
                    const float* s = B + (size_t)(k0 + kk) * ldb + n;
                    asm volatile("cp.async.cg.shared.global [%0], [%1], 16;"
                                 :: "r"(d), "l"(s));
                }
            }
        }
        asm volatile("cp.async.commit_group;" ::: "memory");
    };

    issue(0);
    issue(1);

    for (int kt = 0; kt < nk; ++kt) {
        asm volatile("cp.async.wait_group 1;" ::: "memory");
        __syncthreads();
        issue(kt + 2);

        const float* __restrict__ As = SM + (kt % 3) * STAGE_FLOATS;
        const float* __restrict__ Bs = As + A_FLOATS;
#pragma unroll
        for (int kb8 = 0; kb8 < 4; ++kb8) {
            const int kk = kb8 * 8;
            uint32_t a[2][4], b[NT][2];
#pragma unroll
            for (int mt = 0; mt < 2; ++mt) {
                const int m = warpM * 32 + mt * 16 + g;
                a[mt][0] = __float_as_uint(As[m * 36 + kk + t]);
                a[mt][1] = __float_as_uint(As[(m + 8) * 36 + kk + t]);
                a[mt][2] = __float_as_uint(As[m * 36 + kk + t + 4]);
                a[mt][3] = __float_as_uint(As[(m + 8) * 36 + kk + t + 4]);
            }
#pragma unroll
            for (int nt = 0; nt < NT; ++nt) {
                const int n = warpN * (NT * 8) + nt * 8 + g;
                b[nt][0] = __float_as_uint(Bs[(kk + t) * BPITCH + n]);
                b[nt][1] = __float_as_uint(Bs[(kk + t + 4) * BPITCH + n]);
            }
#pragma unroll
            for (int mt = 0; mt < 2; ++mt)
#pragma unroll
                for (int nt = 0; nt < NT; ++nt)
                    mma_tf32(acc[mt][nt], a[mt], b[nt]);
        }
    }

    if (MODE == 0) {
#pragma unroll
        for (int mt = 0; mt < 2; ++mt) {
#pragma unroll
            for (int nt = 0; nt < NT; ++nt) {
                const int col = n0 + warpN * (NT * 8) + nt * 8 + 2 * t;
                const int row = m0 + warpM * 32 + mt * 16 + g;
                float b0 = 0.f, b1 = 0.f;
                if (bias && col < N) b0 = bias[col];
                if (bias && col + 1 < N) b1 = bias[col + 1];
                if (col + 1 < N) {
                    *(float2*)(C + (size_t)row * ldc + col) =
                        make_float2(acc[mt][nt][0] + b0, acc[mt][nt][1] + b1);
                    *(float2*)(C + (size_t)(row + 8) * ldc + col) =
                        make_float2(acc[mt][nt][2] + b0, acc[mt][nt][3] + b1);
                } else if (col < N) {
                    C[(size_t)row * ldc + col]       = acc[mt][nt][0] + b0;
                    C[(size_t)(row + 8) * ldc + col] = acc[mt][nt][2] + b0;
                }
            }
        }
    } else {
        // fused LSTM gates; C = h_out. Requires NT*16 == BN columns of z.
        __syncthreads();
        float* zs = SM;                       // [64][BN+2]
        constexpr int ZP = BN + 2;
#pragma unroll
        for (int mt = 0; mt < 2; ++mt) {
#pragma unroll
            for (int nt = 0; nt < NT; ++nt) {
                const int c0 = warpN * (NT * 8) + nt * 8 + 2 * t;
                const int r0 = warpM * 32 + mt * 16 + g;
                zs[r0 * ZP + c0]           = acc[mt][nt][0];
                zs[r0 * ZP + c0 + 1]       = acc[mt][nt][1];
                zs[(r0 + 8) * ZP + c0]     = acc[mt][nt][2];
                zs[(r0 + 8) * ZP + c0 + 1] = acc[mt][nt][3];
            }
        }
        __syncthreads();
        const int j0 = n0 >> 2;               // BN/4 j's per tile
        constexpr int NJ = BN / 4;
#pragma unroll
        for (int p = tid; p < 64 * NJ; p += 128) {
            const int r = p & 63, jj = p >> 6;
            const int b = m0 + r, j = j0 + jj;
            const int ch = text[b * NS + step];
            const float* zrow = zs + r * ZP + jj * 4;
            float4 oh = *(const float4*)(lkP + (size_t)(CC + ch) * (4 * HH) + 4 * j);
            float4 bb = *(const float4*)(lbP + 4 * j);
            float zi = zrow[0] + oh.x + bb.x;
            float zf = zrow[1] + oh.y + bb.y;
            float zg = zrow[2] + oh.z + bb.z;
            float zo = zrow[3] + oh.w + bb.w;
            const int ci = b * HH + j;
            float cn = sigm(zf) * g_c[ci] + sigm(zi) * tanhf(zg);
            float hn = to_tf32(sigm(zo) * tanhf(cn));
            g_c[ci] = cn;
            C[ci] = hn;
            g_hs[((size_t)b * NS + step) * HH + j] = hn;
        }
    }
}

// ---------------- prep kernels ------------------------------------------------
__global__ __launch_bounds__(256)
void permute_gates(const float* __restrict__ in, float* __restrict__ out, int total)
{
    int idx = blockIdx.x * 256 + threadIdx.x;
    if (idx >= total) return;
    int row = idx >> 11, oc = idx & 2047;
    int j = oc >> 2, gate = oc & 3;
    out[idx] = to_tf32(in[(size_t)row * 2048 + gate * HH + j]);
}

__global__ __launch_bounds__(256)
void round_copy(const float* __restrict__ in, float* __restrict__ out, int n4)
{
    int i = blockIdx.x * 256 + threadIdx.x;
    if (i >= n4) return;
    float4 v = ((const float4*)in)[i];
    v.x = to_tf32(v.x); v.y = to_tf32(v.y);
    v.z = to_tf32(v.z); v.w = to_tf32(v.w);
    ((float4*)out)[i] = v;
}

// ---------------- fused attention --------------------------------------------
__global__ __launch_bounds__(256)
void attn_kernel(const float* __restrict__ q,
                 const float* __restrict__ batch_H,
                 const float* __restrict__ Ws,
                 float* __restrict__ ctx)
{
    const int b = blockIdx.x;
    __shared__ float qs[HH];
    __shared__ float ws[HH];
    __shared__ float e[TT];

    const int tid = threadIdx.x;
    for (int i = tid; i < HH; i += 256) { qs[i] = q[(size_t)b * HH + i]; ws[i] = Ws[i]; }
    __syncthreads();

    const int warp = tid >> 5, lane = tid & 31;
    for (int t = warp; t < TT; t += 8) {
        const float* __restrict__ hp = g_Hproj + ((size_t)b * TT + t) * HH;
        float p = 0.f;
#pragma unroll 4
        for (int h = lane; h < HH; h += 32)
            p += tanhf(hp[h] + qs[h]) * ws[h];
#pragma unroll
        for (int o = 16; o; o >>= 1) p += __shfl_xor_sync(0xffffffffu, p, o);
        if (lane == 0) e[t] = p;
    }
    __syncthreads();

    if (warp == 0) {
        float v0 = e[lane], v1 = e[lane + 32];
        float m = fmaxf(v0, v1);
#pragma unroll
        for (int o = 16; o; o >>= 1) m = fmaxf(m, __shfl_xor_sync(0xffffffffu, m, o));
        float x0 = __expf(v0 - m), x1 = __expf(v1 - m);
        float s = x0 + x1;
#pragma unroll
        for (int o = 16; o; o >>= 1) s += __shfl_xor_sync(0xffffffffu, s, o);
        float inv = 1.f / s;
        e[lane] = x0 * inv;
        e[lane + 32] = x1 * inv;
    }
    __syncthreads();

    for (int c = tid; c < CC; c += 256) {
        const float* __restrict__ bhp = batch_H + (size_t)b * TT * CC + c;
        float acc = 0.f;
#pragma unroll 8
        for (int t = 0; t < TT; ++t)
            acc = fmaf(e[t], bhp[(size_t)t * CC], acc);
        ctx[(size_t)b * CC + c] = to_tf32(acc);
    }
}

// ---------------- launch -----------------------------------------------------
extern "C" void kernel_launch(void* const* d_in, const int* in_sizes, int n_in,
                              void* d_out, int out_size)
{
    int off = 0;
    if (n_in >= 3 && in_sizes[2] == 1) off = 1;
    const float* batch_H = (const float*)d_in[0];
    const int*   text    = (const int*)  d_in[1];
    const float* Wi      = (const float*)d_in[2 + off];
    const float* Wh      = (const float*)d_in[3 + off];
    const float* bh      = (const float*)d_in[4 + off];
    const float* Ws      = (const float*)d_in[5 + off];
    const float* lk      = (const float*)d_in[6 + off];
    const float* lr      = (const float*)d_in[7 + off];
    const float* lb      = (const float*)d_in[8 + off];
    const float* Wgen    = (const float*)d_in[9 + off];
    const float* bgen    = (const float*)d_in[10 + off];

    float *Hproj, *bh32, *q, *ctx, *hA, *hB, *c, *hs, *lkP, *lrP, *lbP, *wi32, *wh32, *wg32;
    cudaGetSymbolAddress((void**)&Hproj, g_Hproj);
    cudaGetSymbolAddress((void**)&bh32,  g_bh32);
    cudaGetSymbolAddress((void**)&q,     g_q);
    cudaGetSymbolAddress((void**)&ctx,   g_ctx);
    cudaGetSymbolAddress((void**)&hA,    g_hA);
    cudaGetSymbolAddress((void**)&hB,    g_hB);
    cudaGetSymbolAddress((void**)&c,     g_c);
    cudaGetSymbolAddress((void**)&hs,    g_hs);
    cudaGetSymbolAddress((void**)&lkP,   g_lkP);
    cudaGetSymbolAddress((void**)&lrP,   g_lrP);
    cudaGetSymbolAddress((void**)&lbP,   g_lbP);
    cudaGetSymbolAddress((void**)&wi32,  g_wi32);
    cudaGetSymbolAddress((void**)&wh32,  g_wh32);
    cudaGetSymbolAddress((void**)&wg32,  g_wg32);

    // smem sizes: NT=4 -> (2304 + 32*72)*4*3 = 55296 ; NT=8 -> (2304+32*136)*4*3 = 79872
    static bool attr_done = false;
    if (!attr_done) {
        cudaFuncSetAttribute(gemm_cp<0,4>, cudaFuncAttributeMaxDynamicSharedMemorySize, 55296);
        cudaFuncSetAttribute(gemm_cp<0,8>, cudaFuncAttributeMaxDynamicSharedMemorySize, 79872);
        cudaFuncSetAttribute(gemm_cp<1,8>, cudaFuncAttributeMaxDynamicSharedMemorySize, 79872);
        attr_done = true;
    }

    cudaMemsetAsync(hA, 0, (size_t)BB * HH * sizeof(float));
    cudaMemsetAsync(c,  0, (size_t)BB * HH * sizeof(float));

    permute_gates<<<((CC + NCLS) * 4 * HH + 255) / 256, 256>>>(lk, lkP, (CC + NCLS) * 4 * HH);
    permute_gates<<<(HH * 4 * HH + 255) / 256, 256>>>(lr, lrP, HH * 4 * HH);
    permute_gates<<<(4 * HH + 255) / 256, 256>>>(lb, lbP, 4 * HH);
    round_copy<<<(BB * TT * CC / 4 + 255) / 256, 256>>>(batch_H, bh32, BB * TT * CC / 4);
    round_copy<<<(CC * HH / 4 + 255) / 256, 256>>>(Wi, wi32, CC * HH / 4);
    round_copy<<<(HH * HH / 4 + 255) / 256, 256>>>(Wh, wh32, HH * HH / 4);
    round_copy<<<(HH * NCLS / 4 + 255) / 256, 256>>>(Wgen, wg32, HH * NCLS / 4);

    // Hproj = bh32 [B*T, C] @ wi32 [C, H]   (BN=128)
    gemm_cp<0,8><<<dim3(HH / 128, (BB * TT) / 64), 128, 79872>>>(
        bh32, wi32, nullptr, nullptr, nullptr, Hproj,
        BB * TT, HH, CC, CC, HH, HH, nullptr, nullptr, nullptr, 0);

    float* hbuf[2] = { hA, hB };
    for (int s = 0; s < NS; ++s) {
        float* hin  = hbuf[s & 1];
        float* hout = hbuf[(s + 1) & 1];
        // q = h @ Wh + bh   (BN=64, grid 64)
        gemm_cp<0,4><<<dim3(HH / 64, BB / 64), 128, 55296>>>(
            hin, wh32, nullptr, nullptr, bh, q,
            BB, HH, HH, HH, HH, HH, nullptr, nullptr, nullptr, 0);
        attn_kernel<<<BB, 256>>>(q, batch_H, Ws, ctx);
        // fused: z = ctx @ lkP + h @ lrP ; gates   (BN=128, grid 128)
        gemm_cp<1,8><<<dim3((4 * HH) / 128, BB / 64), 128, 79872>>>(
            ctx, lkP, hin, lrP, nullptr, hout,
            BB, 4 * HH, CC, CC, 4 * HH, 4 * HH, lkP, lbP, text, s);
    }

    // probs = hs [B*NS, H] @ wg32 [H, NC] + bgen   (BN=64)
    gemm_cp<0,4><<<dim3((NCLS + 63) / 64, (BB * NS) / 64), 128, 55296>>>(
        hs, wg32, nullptr, nullptr, bgen, (float*)d_out,
        BB * NS, NCLS, HH, HH, NCLS, NCLS, nullptr, nullptr, nullptr, 0);
}

// round 11
// speedup vs baseline: 1.7806x; 1.0434x over previous
#include <cuda_runtime.h>
#include <cuda_bf16.h>
#include <cstdint>

// Problem constants
#define BB   512
#define TT   64
#define CC   512
#define HH   512
#define NCLS 96
#define NS   26

// ---------------- device scratch -------------------------------------------
__device__ float g_Hproj[(size_t)BB * TT * HH];
__device__ float g_bh32 [(size_t)BB * TT * CC];
__device__ float g_q   [(size_t)BB * HH];
__device__ float g_ctx [(size_t)BB * HH];
__device__ float g_hA  [(size_t)BB * HH];
__device__ float g_hB  [(size_t)BB * HH];
__device__ float g_c   [(size_t)BB * HH];
__device__ float g_hs  [(size_t)BB * NS * HH];
__device__ float g_lkP [(size_t)(CC + NCLS) * 4 * HH];
__device__ float g_lrP [(size_t)HH * 4 * HH];
__device__ float g_lbP [(size_t)4 * HH];
__device__ float g_wi32[(size_t)CC * HH];
__device__ float g_wh32[(size_t)HH * HH];
__device__ float g_wg32[(size_t)HH * NCLS];

// ---------------- helpers ----------------------------------------------------
__device__ __forceinline__ float to_tf32(float x) {
    uint32_t r;
    asm("cvt.rna.tf32.f32 %0, %1;" : "=r"(r) : "f"(x));
    return __uint_as_float(r);
}
__device__ __forceinline__ void mma_tf32(float* d, const uint32_t* a, const uint32_t* b) {
    asm volatile(
        "mma.sync.aligned.m16n8k8.row.col.f32.tf32.tf32.f32 "
        "{%0,%1,%2,%3}, {%4,%5,%6,%7}, {%8,%9}, {%0,%1,%2,%3};"
        : "+f"(d[0]), "+f"(d[1]), "+f"(d[2]), "+f"(d[3])
        : "r"(a[0]), "r"(a[1]), "r"(a[2]), "r"(a[3]),
          "r"(b[0]), "r"(b[1]));
}
__device__ __forceinline__ float sigm(float x) { return 1.f / (1.f + __expf(-x)); }

// ---------------- cp.async 3-stage tf32 GEMM --------------------------------
// Block tile 64 x (NT*16), BK=32, 128 threads, 4 warps, warp tile 32 x (NT*8).
// Fragment loads software-pipelined across kb8 (ping-pong registers).
#define A_FLOATS 2304

template<int MODE, int NT>
__global__ __launch_bounds__(128)
void gemm_cp(const float* __restrict__ A1, const float* __restrict__ B1,
             const float* __restrict__ A2, const float* __restrict__ B2,
             const float* __restrict__ bias, float* __restrict__ C,
             int M, int N, int K, int lda, int ldb, int ldc,
             const float* __restrict__ lkP, const float* __restrict__ lbP,
             const int* __restrict__ text, int step)
{
    constexpr int BN = NT * 16;
    constexpr int BPITCH = BN + 8;
    constexpr int B_FLOATS = 32 * BPITCH;
    constexpr int STAGE_FLOATS = A_FLOATS + B_FLOATS;
    constexpr int STAGE_BYTES = STAGE_FLOATS * 4;
    constexpr int BCHUNK = BN / 4;

    extern __shared__ float SM[];
    const int tid = threadIdx.x;
    const int wid = tid >> 5, lane = tid & 31;
    const int warpM = wid >> 1, warpN = wid & 1;
    const int g = lane >> 2, t = lane & 3;
    const int m0 = blockIdx.y * 64, n0 = blockIdx.x * BN;
    const int kpt = K / 32;
    const int npass = (A2 != nullptr) ? 2 : 1;
    const int nk = kpt * npass;
    const uint32_t sbase = (uint32_t)__cvta_generic_to_shared(SM);

    if (n0 + BN > N) {
        for (int st = 0; st < 3; ++st)
            for (int i = tid; i < B_FLOATS; i += 128)
                SM[st * STAGE_FLOATS + A_FLOATS + i] = 0.f;
        __syncthreads();
    }

    float acc[2][NT][4];
#pragma unroll
    for (int i = 0; i < 2; ++i)
#pragma unroll
        for (int j = 0; j < NT; ++j)
#pragma unroll
            for (int k = 0; k < 4; ++k) acc[i][j][k] = 0.f;

    auto issue = [&](int kt) {
        if (kt < nk) {
            const int pass = kt / kpt;
            const int k0 = (kt - pass * kpt) * 32;
            const float* __restrict__ A = pass ? A2 : A1;
            const float* __restrict__ B = pass ? B2 : B1;
            const uint32_t ab = sbase + (uint32_t)(kt % 3) * STAGE_BYTES;
            const uint32_t bb = ab + A_FLOATS * 4;
#pragma unroll
            for (int i = 0; i < 4; ++i) {
                const int lin = tid + 128 * i;
                const int row = lin >> 3, q = lin & 7;
                const uint32_t d = ab + (uint32_t)(row * 36 + q * 4) * 4u;
                const float* s = A + (size_t)(m0 + row) * lda + k0 + q * 4;
                asm volatile("cp.async.cg.shared.global [%0], [%1], 16;"
                             :: "r"(d), "l"(s));
            }
#pragma unroll
            for (int i = 0; i < NT; ++i) {
                const int lin = tid + 128 * i;
                const int kk = lin / BCHUNK, q = lin % BCHUNK;
                const int n = n0 + q * 4;
                if (n + 3 < N) {
                    const uint32_t d = bb + (uint32_t)(kk * BPITCH + q * 4) * 4u;
                    const float* s = B + (size_t)(k0 + kk) * ldb + n;
                    asm volatile("cp.async.cg.shared.global [%0], [%1], 16;"
                                 :: "r"(d), "l"(s));
                }
            }
        }
        asm volatile("cp.async.commit_group;" ::: "memory");
    };

    issue(0);
    issue(1);

    for (int kt = 0; kt < nk; ++kt) {
        asm volatile("cp.async.wait_group 1;" ::: "memory");
        __syncthreads();
        issue(kt + 2);

        const float* __restrict__ As = SM + (kt % 3) * STAGE_FLOATS;
        const float* __restrict__ Bs = As + A_FLOATS;

        // fragment ping-pong: load kb8+1 while issuing MMAs for kb8
        uint32_t fa[2][2][4], fb[2][NT][2];
        auto ldfrag = [&](int kb8, int slot) {
            const int kk = kb8 * 8;
#pragma unroll
            for (int mt = 0; mt < 2; ++mt) {
                const int m = warpM * 32 + mt * 16 + g;
                fa[slot][mt][0] = __float_as_uint(As[m * 36 + kk + t]);
                fa[slot][mt][1] = __float_as_uint(As[(m + 8) * 36 + kk + t]);
                fa[slot][mt][2] = __float_as_uint(As[m * 36 + kk + t + 4]);
                fa[slot][mt][3] = __float_as_uint(As[(m + 8) * 36 + kk + t + 4]);
            }
#pragma unroll
            for (int nt = 0; nt < NT; ++nt) {
                const int n = warpN * (NT * 8) + nt * 8 + g;
                fb[slot][nt][0] = __float_as_uint(Bs[(kk + t) * BPITCH + n]);
                fb[slot][nt][1] = __float_as_uint(Bs[(kk + t + 4) * BPITCH + n]);
            }
        };

        ldfrag(0, 0);
#pragma unroll
        for (int kb8 = 0; kb8 < 4; ++kb8) {
            const int cur = kb8 & 1, nxt = cur ^ 1;
            if (kb8 < 3) ldfrag(kb8 + 1, nxt);
#pragma unroll
            for (int mt = 0; mt < 2; ++mt)
#pragma unroll
                for (int nt = 0; nt < NT; ++nt)
                    mma_tf32(acc[mt][nt], fa[cur][mt], fb[cur][nt]);
        }
    }

    if (MODE == 0) {
#pragma unroll
        for (int mt = 0; mt < 2; ++mt) {
#pragma unroll
            for (int nt = 0; nt < NT; ++nt) {
                const int col = n0 + warpN * (NT * 8) + nt * 8 + 2 * t;
                const int row = m0 + warpM * 32 + mt * 16 + g;
                float b0 = 0.f, b1 = 0.f;
                if (bias && col < N) b0 = bias[col];
                if (bias && col + 1 < N) b1 = bias[col + 1];
                if (col + 1 < N) {
                    *(float2*)(C + (size_t)row * ldc + col) =
                        make_float2(acc[mt][nt][0] + b0, acc[mt][nt][1] + b1);
                    *(float2*)(C + (size_t)(row + 8) * ldc + col) =
                        make_float2(acc[mt][nt][2] + b0, acc[mt][nt][3] + b1);
                } else if (col < N) {
                    C[(size_t)row * ldc + col]       = acc[mt][nt][0] + b0;
                    C[(size_t)(row + 8) * ldc + col] = acc[mt][nt][2] + b0;
                }
            }
        }
    } else {
        // fused LSTM gates; C = h_out (double-buffered).
        __syncthreads();
        float* zs = SM;
        constexpr int ZP = BN + 2;
#pragma unroll
        for (int mt = 0; mt < 2; ++mt) {
#pragma unroll
            for (int nt = 0; nt < NT; ++nt) {
                const int c0 = warpN * (NT * 8) + nt * 8 + 2 * t;
                const int r0 = warpM * 32 + mt * 16 + g;
                zs[r0 * ZP + c0]           = acc[mt][nt][0];
                zs[r0 * ZP + c0 + 1]       = acc[mt][nt][1];
                zs[(r0 + 8) * ZP + c0]     = acc[mt][nt][2];
                zs[(r0 + 8) * ZP + c0 + 1] = acc[mt][nt][3];
            }
        }
        __syncthreads();
        const int j0 = n0 >> 2;
        constexpr int NJ = BN / 4;
#pragma unroll
        for (int p = tid; p < 64 * NJ; p += 128) {
            const int r = p & 63, jj = p >> 6;
            const int b = m0 + r, j = j0 + jj;
            const int ch = text[b * NS + step];
            const float* zrow = zs + r * ZP + jj * 4;
            float4 oh = *(const float4*)(lkP + (size_t)(CC + ch) * (4 * HH) + 4 * j);
            float4 bb = *(const float4*)(lbP + 4 * j);
            float zi = zrow[0] + oh.x + bb.x;
            float zf = zrow[1] + oh.y + bb.y;
            float zg = zrow[2] + oh.z + bb.z;
            float zo = zrow[3] + oh.w + bb.w;
            const int ci = b * HH + j;
            float cn = sigm(zf) * g_c[ci] + sigm(zi) * tanhf(zg);
            float hn = to_tf32(sigm(zo) * tanhf(cn));
            g_c[ci] = cn;
            C[ci] = hn;
            g_hs[((size_t)b * NS + step) * HH + j] = hn;
        }
    }
}

// ---------------- prep kernels ------------------------------------------------
__global__ __launch_bounds__(256)
void permute_gates(const float* __restrict__ in, float* __restrict__ out, int total)
{
    int idx = blockIdx.x * 256 + threadIdx.x;
    if (idx >= total) return;
    int row = idx >> 11, oc = idx & 2047;
    int j = oc >> 2, gate = oc & 3;
    out[idx] = to_tf32(in[(size_t)row * 2048 + gate * HH + j]);
}

__global__ __launch_bounds__(256)
void round_copy(const float* __restrict__ in, float* __restrict__ out, int n4)
{
    int i = blockIdx.x * 256 + threadIdx.x;
    if (i >= n4) return;
    float4 v = ((const float4*)in)[i];
    v.x = to_tf32(v.x); v.y = to_tf32(v.y);
    v.z = to_tf32(v.z); v.w = to_tf32(v.w);
    ((float4*)out)[i] = v;
}

// ---------------- fused attention --------------------------------------------
__global__ __launch_bounds__(256)
void attn_kernel(const float* __restrict__ q,
                 const float* __restrict__ batch_H,
                 const float* __restrict__ Ws,
                 float* __restrict__ ctx)
{
    const int b = blockIdx.x;
    __shared__ float qs[HH];
    __shared__ float ws[HH];
    __shared__ float e[TT];

    const int tid = threadIdx.x;
    for (int i = tid; i < HH; i += 256) { qs[i] = q[(size_t)b * HH + i]; ws[i] = Ws[i]; }
    __syncthreads();

    const int warp = tid >> 5, lane = tid & 31;
    for (int t = warp; t < TT; t += 8) {
        const float* __restrict__ hp = g_Hproj + ((size_t)b * TT + t) * HH;
        float p = 0.f;
#pragma unroll 4
        for (int h = lane; h < HH; h += 32)
            p += tanhf(hp[h] + qs[h]) * ws[h];
#pragma unroll
        for (int o = 16; o; o >>= 1) p += __shfl_xor_sync(0xffffffffu, p, o);
        if (lane == 0) e[t] = p;
    }
    __syncthreads();

    if (warp == 0) {
        float v0 = e[lane], v1 = e[lane + 32];
        float m = fmaxf(v0, v1);
#pragma unroll
        for (int o = 16; o; o >>= 1) m = fmaxf(m, __shfl_xor_sync(0xffffffffu, m, o));
        float x0 = __expf(v0 - m), x1 = __expf(v1 - m);
        float s = x0 + x1;
#pragma unroll
        for (int o = 16; o; o >>= 1) s += __shfl_xor_sync(0xffffffffu, s, o);
        float inv = 1.f / s;
        e[lane] = x0 * inv;
        e[lane + 32] = x1 * inv;
    }
    __syncthreads();

    for (int c = tid; c < CC; c += 256) {
        const float* __restrict__ bhp = batch_H + (size_t)b * TT * CC + c;
        float acc = 0.f;
#pragma unroll 8
        for (int t = 0; t < TT; ++t)
            acc = fmaf(e[t], bhp[(size_t)t * CC], acc);
        ctx[(size_t)b * CC + c] = to_tf32(acc);
    }
}

// ---------------- launch -----------------------------------------------------
extern "C" void kernel_launch(void* const* d_in, const int* in_sizes, int n_in,
                              void* d_out, int out_size)
{
    int off = 0;
    if (n_in >= 3 && in_sizes[2] == 1) off = 1;
    const float* batch_H = (const float*)d_in[0];
    const int*   text    = (const int*)  d_in[1];
    const float* Wi      = (const float*)d_in[2 + off];
    const float* Wh      = (const float*)d_in[3 + off];
    const float* bh      = (const float*)d_in[4 + off];
    const float* Ws      = (const float*)d_in[5 + off];
    const float* lk      = (const float*)d_in[6 + off];
    const float* lr      = (const float*)d_in[7 + off];
    const float* lb      = (const float*)d_in[8 + off];
    const float* Wgen    = (const float*)d_in[9 + off];
    const float* bgen    = (const float*)d_in[10 + off];

    float *Hproj, *bh32, *q, *ctx, *hA, *hB, *c, *hs, *lkP, *lrP, *lbP, *wi32, *wh32, *wg32;
    cudaGetSymbolAddress((void**)&Hproj, g_Hproj);
    cudaGetSymbolAddress((void**)&bh32,  g_bh32);
    cudaGetSymbolAddress((void**)&q,     g_q);
    cudaGetSymbolAddress((void**)&ctx,   g_ctx);
    cudaGetSymbolAddress((void**)&hA,    g_hA);
    cudaGetSymbolAddress((void**)&hB,    g_hB);
    cudaGetSymbolAddress((void**)&c,     g_c);
    cudaGetSymbolAddress((void**)&hs,    g_hs);
    cudaGetSymbolAddress((void**)&lkP,   g_lkP);
    cudaGetSymbolAddress((void**)&lrP,   g_lrP);
    cudaGetSymbolAddress((void**)&lbP,   g_lbP);
    cudaGetSymbolAddress((void**)&wi32,  g_wi32);
    cudaGetSymbolAddress((void**)&wh32,  g_wh32);
    cudaGetSymbolAddress((void**)&wg32,  g_wg32);

    // smem: NT=2 -> (2304+32*40)*12 = 43008 ; NT=8 -> (2304+32*136)*12 = 79872
    static bool attr_done = false;
    if (!attr_done) {
        cudaFuncSetAttribute(gemm_cp<0,2>, cudaFuncAttributeMaxDynamicSharedMemorySize, 43008);
        cudaFuncSetAttribute(gemm_cp<0,8>, cudaFuncAttributeMaxDynamicSharedMemorySize, 79872);
        cudaFuncSetAttribute(gemm_cp<1,8>, cudaFuncAttributeMaxDynamicSharedMemorySize, 79872);
        attr_done = true;
    }

    cudaMemsetAsync(hA, 0, (size_t)BB * HH * sizeof(float));
    cudaMemsetAsync(c,  0, (size_t)BB * HH * sizeof(float));

    permute_gates<<<((CC + NCLS) * 4 * HH + 255) / 256, 256>>>(lk, lkP, (CC + NCLS) * 4 * HH);
    permute_gates<<<(HH * 4 * HH + 255) / 256, 256>>>(lr, lrP, HH * 4 * HH);
    permute_gates<<<(4 * HH + 255) / 256, 256>>>(lb, lbP, 4 * HH);
    round_copy<<<(BB * TT * CC / 4 + 255) / 256, 256>>>(batch_H, bh32, BB * TT * CC / 4);
    round_copy<<<(CC * HH / 4 + 255) / 256, 256>>>(Wi, wi32, CC * HH / 4);
    round_copy<<<(HH * HH / 4 + 255) / 256, 256>>>(Wh, wh32, HH * HH / 4);
    round_copy<<<(HH * NCLS / 4 + 255) / 256, 256>>>(Wgen, wg32, HH * NCLS / 4);

    // Hproj = bh32 [B*T, C] @ wi32 [C, H]   (BN=128, grid 2048)
    gemm_cp<0,8><<<dim3(HH / 128, (BB * TT) / 64), 128, 79872>>>(
        bh32, wi32, nullptr, nullptr, nullptr, Hproj,
        BB * TT, HH, CC, CC, HH, HH, nullptr, nullptr, nullptr, 0);

    float* hbuf[2] = { hA, hB };
    for (int s = 0; s < NS; ++s) {
        float* hin  = hbuf[s & 1];
        float* hout = hbuf[(s + 1) & 1];
        // q = h @ Wh + bh   (BN=32, grid 128)
        gemm_cp<0,2><<<dim3(HH / 32, BB / 64), 128, 43008>>>(
            hin, wh32, nullptr, nullptr, bh, q,
            BB, HH, HH, HH, HH, HH, nullptr, nullptr, nullptr, 0);
        attn_kernel<<<BB, 256>>>(q, batch_H, Ws, ctx);
        // fused: z = ctx @ lkP + h @ lrP ; gates   (BN=128, grid 128)
        gemm_cp<1,8><<<dim3((4 * HH) / 128, BB / 64), 128, 79872>>>(
            ctx, lkP, hin, lrP, nullptr, hout,
            BB, 4 * HH, CC, CC, 4 * HH, 4 * HH, lkP, lbP, text, s);
    }

    // probs = hs [B*NS, H] @ wg32 [H, NC] + bgen   (BN=32, N=96 exact)
    gemm_cp<0,2><<<dim3(NCLS / 32, (BB * NS) / 64), 128, 43008>>>(
        hs, wg32, nullptr, nullptr, bgen, (float*)d_out,
        BB * NS, NCLS, HH, HH, NCLS, NCLS, nullptr, nullptr, nullptr, 0);
}

// round 12
// speedup vs baseline: 2.1726x; 1.2202x over previous
#include <cuda_runtime.h>
#include <cuda_bf16.h>
#include <cuda_fp16.h>
#include <cstdint>

// Problem constants
#define BB   512
#define TT   64
#define CC   512
#define HH   512
#define NCLS 96
#define NS   26

// ---------------- device scratch -------------------------------------------
__device__ __half g_hp16[(size_t)BB * TT * HH];   // fp16 Hproj (33.5 MB)
__device__ __half g_bh16[(size_t)BB * TT * CC];   // fp16 batch_H (33.5 MB)
__device__ float g_bh32 [(size_t)BB * TT * CC];
__device__ float g_q   [(size_t)BB * HH];
__device__ float g_ctx [(size_t)BB * HH];
__device__ float g_hA  [(size_t)BB * HH];
__device__ float g_hB  [(size_t)BB * HH];
__device__ float g_c   [(size_t)BB * HH];
__device__ float g_hs  [(size_t)BB * NS * HH];
__device__ float g_lkP [(size_t)(CC + NCLS) * 4 * HH];
__device__ float g_lrP [(size_t)HH * 4 * HH];
__device__ float g_lbP [(size_t)4 * HH];
__device__ float g_wi32[(size_t)CC * HH];
__device__ float g_wh32[(size_t)HH * HH];
__device__ float g_wg32[(size_t)HH * NCLS];

// ---------------- helpers ----------------------------------------------------
__device__ __forceinline__ float to_tf32(float x) {
    uint32_t r;
    asm("cvt.rna.tf32.f32 %0, %1;" : "=r"(r) : "f"(x));
    return __uint_as_float(r);
}
__device__ __forceinline__ void mma_tf32(float* d, const uint32_t* a, const uint32_t* b) {
    asm volatile(
        "mma.sync.aligned.m16n8k8.row.col.f32.tf32.tf32.f32 "
        "{%0,%1,%2,%3}, {%4,%5,%6,%7}, {%8,%9}, {%0,%1,%2,%3};"
        : "+f"(d[0]), "+f"(d[1]), "+f"(d[2]), "+f"(d[3])
        : "r"(a[0]), "r"(a[1]), "r"(a[2]), "r"(a[3]),
          "r"(b[0]), "r"(b[1]));
}
__device__ __forceinline__ float sigm(float x) { return 1.f / (1.f + __expf(-x)); }

// ---------------- cp.async 3-stage tf32 GEMM --------------------------------
// Block tile 64 x (NT*16), BK=32, 128 threads, 4 warps, warp tile 32 x (NT*8).
// MODE 0: fp32 C (+bias). MODE 1: fused LSTM gates. MODE 2: fp16 C output.
#define A_FLOATS 2304

template<int MODE, int NT>
__global__ __launch_bounds__(128)
void gemm_cp(const float* __restrict__ A1, const float* __restrict__ B1,
             const float* __restrict__ A2, const float* __restrict__ B2,
             const float* __restrict__ bias, float* __restrict__ C,
             int M, int N, int K, int lda, int ldb, int ldc,
             const float* __restrict__ lkP, const float* __restrict__ lbP,
             const int* __restrict__ text, int step)
{
    constexpr int BN = NT * 16;
    constexpr int BPITCH = BN + 8;
    constexpr int B_FLOATS = 32 * BPITCH;
    constexpr int STAGE_FLOATS = A_FLOATS + B_FLOATS;
    constexpr int STAGE_BYTES = STAGE_FLOATS * 4;
    constexpr int BCHUNK = BN / 4;

    extern __shared__ float SM[];
    const int tid = threadIdx.x;
    const int wid = tid >> 5, lane = tid & 31;
    const int warpM = wid >> 1, warpN = wid & 1;
    const int g = lane >> 2, t = lane & 3;
    const int m0 = blockIdx.y * 64, n0 = blockIdx.x * BN;
    const int kpt = K / 32;
    const int npass = (A2 != nullptr) ? 2 : 1;
    const int nk = kpt * npass;
    const uint32_t sbase = (uint32_t)__cvta_generic_to_shared(SM);

    if (n0 + BN > N) {
        for (int st = 0; st < 3; ++st)
            for (int i = tid; i < B_FLOATS; i += 128)
                SM[st * STAGE_FLOATS + A_FLOATS + i] = 0.f;
        __syncthreads();
    }

    float acc[2][NT][4];
#pragma unroll
    for (int i = 0; i < 2; ++i)
#pragma unroll
        for (int j = 0; j < NT; ++j)
#pragma unroll
            for (int k = 0; k < 4; ++k) acc[i][j][k] = 0.f;

    auto issue = [&](int kt) {
        if (kt < nk) {
            const int pass = kt / kpt;
            const int k0 = (kt - pass * kpt) * 32;
            const float* __restrict__ A = pass ? A2 : A1;
            const float* __restrict__ B = pass ? B2 : B1;
            const uint32_t ab = sbase + (uint32_t)(kt % 3) * STAGE_BYTES;
            const uint32_t bb = ab + A_FLOATS * 4;
#pragma unroll
            for (int i = 0; i < 4; ++i) {
                const int lin = tid + 128 * i;
                const int row = lin >> 3, q = lin & 7;
                const uint32_t d = ab + (uint32_t)(row * 36 + q * 4) * 4u;
                const float* s = A + (size_t)(m0 + row) * lda + k0 + q * 4;
                asm volatile("cp.async.cg.shared.global [%0], [%1], 16;"
                             :: "r"(d), "l"(s));
            }
#pragma unroll
            for (int i = 0; i < NT; ++i) {
                const int lin = tid + 128 * i;
                const int kk = lin / BCHUNK, q = lin % BCHUNK;
                const int n = n0 + q * 4;
                if (n + 3 < N) {
                    const uint32_t d = bb + (uint32_t)(kk * BPITCH + q * 4) * 4u;
                    const float* s = B + (size_t)(k0 + kk) * ldb + n;
                    asm volatile("cp.async.cg.shared.global [%0], [%1], 16;"
                                 :: "r"(d), "l"(s));
                }
            }
        }
        asm volatile("cp.async.commit_group;" ::: "memory");
    };

    issue(0);
    issue(1);

    for (int kt = 0; kt < nk; ++kt) {
        asm volatile("cp.async.wait_group 1;" ::: "memory");
        __syncthreads();
        issue(kt + 2);

        const float* __restrict__ As = SM + (kt % 3) * STAGE_FLOATS;
        const float* __restrict__ Bs = As + A_FLOATS;

        uint32_t fa[2][2][4], fb[2][NT][2];
        auto ldfrag = [&](int kb8, int slot) {
            const int kk = kb8 * 8;
#pragma unroll
            for (int mt = 0; mt < 2; ++mt) {
                const int m = warpM * 32 + mt * 16 + g;
                fa[slot][mt][0] = __float_as_uint(As[m * 36 + kk + t]);
                fa[slot][mt][1] = __float_as_uint(As[(m + 8) * 36 + kk + t]);
                fa[slot][mt][2] = __float_as_uint(As[m * 36 + kk + t + 4]);
                fa[slot][mt][3] = __float_as_uint(As[(m + 8) * 36 + kk + t + 4]);
            }
#pragma unroll
            for (int nt = 0; nt < NT; ++nt) {
                const int n = warpN * (NT * 8) + nt * 8 + g;
                fb[slot][nt][0] = __float_as_uint(Bs[(kk + t) * BPITCH + n]);
                fb[slot][nt][1] = __float_as_uint(Bs[(kk + t + 4) * BPITCH + n]);
            }
        };

        ldfrag(0, 0);
#pragma unroll
        for (int kb8 = 0; kb8 < 4; ++kb8) {
            const int cur = kb8 & 1, nxt = cur ^ 1;
            if (kb8 < 3) ldfrag(kb8 + 1, nxt);
#pragma unroll
            for (int mt = 0; mt < 2; ++mt)
#pragma unroll
                for (int nt = 0; nt < NT; ++nt)
                    mma_tf32(acc[mt][nt], fa[cur][mt], fb[cur][nt]);
        }
    }

    if (MODE == 0) {
#pragma unroll
        for (int mt = 0; mt < 2; ++mt) {
#pragma unroll
            for (int nt = 0; nt < NT; ++nt) {
                const int col = n0 + warpN * (NT * 8) + nt * 8 + 2 * t;
                const int row = m0 + warpM * 32 + mt * 16 + g;
                float b0 = 0.f, b1 = 0.f;
                if (bias && col < N) b0 = bias[col];
                if (bias && col + 1 < N) b1 = bias[col + 1];
                if (col + 1 < N) {
                    *(float2*)(C + (size_t)row * ldc + col) =
                        make_float2(acc[mt][nt][0] + b0, acc[mt][nt][1] + b1);
                    *(float2*)(C + (size_t)(row + 8) * ldc + col) =
                        make_float2(acc[mt][nt][2] + b0, acc[mt][nt][3] + b1);
                } else if (col < N) {
                    C[(size_t)row * ldc + col]       = acc[mt][nt][0] + b0;
                    C[(size_t)(row + 8) * ldc + col] = acc[mt][nt][2] + b0;
                }
            }
        }
    } else if (MODE == 2) {
        // fp16 output (Hproj). N multiple of BN assumed here (512/128 ok).
        __half* C16 = (__half*)C;
#pragma unroll
        for (int mt = 0; mt < 2; ++mt) {
#pragma unroll
            for (int nt = 0; nt < NT; ++nt) {
                const int col = n0 + warpN * (NT * 8) + nt * 8 + 2 * t;
                const int row = m0 + warpM * 32 + mt * 16 + g;
                *(__half2*)(C16 + (size_t)row * ldc + col) =
                    __floats2half2_rn(acc[mt][nt][0], acc[mt][nt][1]);
                *(__half2*)(C16 + (size_t)(row + 8) * ldc + col) =
                    __floats2half2_rn(acc[mt][nt][2], acc[mt][nt][3]);
            }
        }
    } else {
        // fused LSTM gates; C = h_out (double-buffered).
        __syncthreads();
        float* zs = SM;
        constexpr int ZP = BN + 2;
#pragma unroll
        for (int mt = 0; mt < 2; ++mt) {
#pragma unroll
            for (int nt = 0; nt < NT; ++nt) {
                const int c0 = warpN * (NT * 8) + nt * 8 + 2 * t;
                const int r0 = warpM * 32 + mt * 16 + g;
                zs[r0 * ZP + c0]           = acc[mt][nt][0];
                zs[r0 * ZP + c0 + 1]       = acc[mt][nt][1];
                zs[(r0 + 8) * ZP + c0]     = acc[mt][nt][2];
                zs[(r0 + 8) * ZP + c0 + 1] = acc[mt][nt][3];
            }
        }
        __syncthreads();
        const int j0 = n0 >> 2;
        constexpr int NJ = BN / 4;
#pragma unroll
        for (int p = tid; p < 64 * NJ; p += 128) {
            const int r = p & 63, jj = p >> 6;
            const int b = m0 + r, j = j0 + jj;
            const int ch = text[b * NS + step];
            const float* zrow = zs + r * ZP + jj * 4;
            float4 oh = *(const float4*)(lkP + (size_t)(CC + ch) * (4 * HH) + 4 * j);
            float4 bb = *(const float4*)(lbP + 4 * j);
            float zi = zrow[0] + oh.x + bb.x;
            float zf = zrow[1] + oh.y + bb.y;
            float zg = zrow[2] + oh.z + bb.z;
            float zo = zrow[3] + oh.w + bb.w;
            const int ci = b * HH + j;
            float cn = sigm(zf) * g_c[ci] + sigm(zi) * tanhf(zg);
            float hn = to_tf32(sigm(zo) * tanhf(cn));
            g_c[ci] = cn;
            C[ci] = hn;
            g_hs[((size_t)b * NS + step) * HH + j] = hn;
        }
    }
}

// ---------------- prep kernels ------------------------------------------------
__global__ __launch_bounds__(256)
void permute_gates(const float* __restrict__ in, float* __restrict__ out, int total)
{
    int idx = blockIdx.x * 256 + threadIdx.x;
    if (idx >= total) return;
    int row = idx >> 11, oc = idx & 2047;
    int j = oc >> 2, gate = oc & 3;
    out[idx] = to_tf32(in[(size_t)row * 2048 + gate * HH + j]);
}

__global__ __launch_bounds__(256)
void round_copy(const float* __restrict__ in, float* __restrict__ out, int n4)
{
    int i = blockIdx.x * 256 + threadIdx.x;
    if (i >= n4) return;
    float4 v = ((const float4*)in)[i];
    v.x = to_tf32(v.x); v.y = to_tf32(v.y);
    v.z = to_tf32(v.z); v.w = to_tf32(v.w);
    ((float4*)out)[i] = v;
}

__global__ __launch_bounds__(256)
void half_copy(const float* __restrict__ in, __half* __restrict__ out, int n4)
{
    int i = blockIdx.x * 256 + threadIdx.x;
    if (i >= n4) return;
    float4 v = ((const float4*)in)[i];
    __half2 h0 = __floats2half2_rn(v.x, v.y);
    __half2 h1 = __floats2half2_rn(v.z, v.w);
    ((__half2*)out)[2 * i]     = h0;
    ((__half2*)out)[2 * i + 1] = h1;
}

// ---------------- fused attention (fp16 Hproj + batch_H) ---------------------
__global__ __launch_bounds__(256)
void attn_kernel(const float* __restrict__ q,
                 const __half* __restrict__ hp16,
                 const __half* __restrict__ bh16,
                 const float* __restrict__ Ws,
                 float* __restrict__ ctx)
{
    const int b = blockIdx.x;
    __shared__ float qs[HH];
    __shared__ float ws[HH];
    __shared__ float e[TT];

    const int tid = threadIdx.x;
    for (int i = tid; i < HH; i += 256) { qs[i] = q[(size_t)b * HH + i]; ws[i] = Ws[i]; }
    __syncthreads();

    const int warp = tid >> 5, lane = tid & 31;
    for (int t = warp; t < TT; t += 8) {
        const __half2* __restrict__ hp =
            (const __half2*)(hp16 + ((size_t)b * TT + t) * HH);
        float p = 0.f;
#pragma unroll
        for (int j = 0; j < 8; ++j) {
            const int idx = lane + 32 * j;             // half2 index, 256 total
            float2 f = __half22float2(hp[idx]);
            float2 qv = *(const float2*)&qs[2 * idx];
            float2 wv = *(const float2*)&ws[2 * idx];
            p += tanhf(f.x + qv.x) * wv.x + tanhf(f.y + qv.y) * wv.y;
        }
#pragma unroll
        for (int o = 16; o; o >>= 1) p += __shfl_xor_sync(0xffffffffu, p, o);
        if (lane == 0) e[t] = p;
    }
    __syncthreads();

    if (warp == 0) {
        float v0 = e[lane], v1 = e[lane + 32];
        float m = fmaxf(v0, v1);
#pragma unroll
        for (int o = 16; o; o >>= 1) m = fmaxf(m, __shfl_xor_sync(0xffffffffu, m, o));
        float x0 = __expf(v0 - m), x1 = __expf(v1 - m);
        float s = x0 + x1;
#pragma unroll
        for (int o = 16; o; o >>= 1) s += __shfl_xor_sync(0xffffffffu, s, o);
        float inv = 1.f / s;
        e[lane] = x0 * inv;
        e[lane + 32] = x1 * inv;
    }
    __syncthreads();

    // context: thread owns half2 column pair (cols 2*tid, 2*tid+1)
    {
        const __half2* __restrict__ bp =
            (const __half2*)(bh16 + (size_t)b * TT * CC);
        float2 acc = make_float2(0.f, 0.f);
#pragma unroll 8
        for (int t = 0; t < TT; ++t) {
            float2 f = __half22float2(bp[t * (CC / 2) + tid]);
            float a = e[t];
            acc.x = fmaf(a, f.x, acc.x);
            acc.y = fmaf(a, f.y, acc.y);
        }
        ctx[(size_t)b * CC + 2 * tid]     = to_tf32(acc.x);
        ctx[(size_t)b * CC + 2 * tid + 1] = to_tf32(acc.y);
    }
}

// ---------------- launch -----------------------------------------------------
extern "C" void kernel_launch(void* const* d_in, const int* in_sizes, int n_in,
                              void* d_out, int out_size)
{
    int off = 0;
    if (n_in >= 3 && in_sizes[2] == 1) off = 1;
    const float* batch_H = (const float*)d_in[0];
    const int*   text    = (const int*)  d_in[1];
    const float* Wi      = (const float*)d_in[2 + off];
    const float* Wh      = (const float*)d_in[3 + off];
    const float* bh      = (const float*)d_in[4 + off];
    const float* Ws      = (const float*)d_in[5 + off];
    const float* lk      = (const float*)d_in[6 + off];
    const float* lr      = (const float*)d_in[7 + off];
    const float* lb      = (const float*)d_in[8 + off];
    const float* Wgen    = (const float*)d_in[9 + off];
    const float* bgen    = (const float*)d_in[10 + off];

    float *bh32, *q, *ctx, *hA, *hB, *c, *hs, *lkP, *lrP, *lbP, *wi32, *wh32, *wg32;
    __half *hp16, *bh16;
    cudaGetSymbolAddress((void**)&hp16,  g_hp16);
    cudaGetSymbolAddress((void**)&bh16,  g_bh16);
    cudaGetSymbolAddress((void**)&bh32,  g_bh32);
    cudaGetSymbolAddress((void**)&q,     g_q);
    cudaGetSymbolAddress((void**)&ctx,   g_ctx);
    cudaGetSymbolAddress((void**)&hA,    g_hA);
    cudaGetSymbolAddress((void**)&hB,    g_hB);
    cudaGetSymbolAddress((void**)&c,     g_c);
    cudaGetSymbolAddress((void**)&hs,    g_hs);
    cudaGetSymbolAddress((void**)&lkP,   g_lkP);
    cudaGetSymbolAddress((void**)&lrP,   g_lrP);
    cudaGetSymbolAddress((void**)&lbP,   g_lbP);
    cudaGetSymbolAddress((void**)&wi32,  g_wi32);
    cudaGetSymbolAddress((void**)&wh32,  g_wh32);
    cudaGetSymbolAddress((void**)&wg32,  g_wg32);

    static bool attr_done = false;
    if (!attr_done) {
        cudaFuncSetAttribute(gemm_cp<0,2>, cudaFuncAttributeMaxDynamicSharedMemorySize, 43008);
        cudaFuncSetAttribute(gemm_cp<2,8>, cudaFuncAttributeMaxDynamicSharedMemorySize, 79872);
        cudaFuncSetAttribute(gemm_cp<1,8>, cudaFuncAttributeMaxDynamicSharedMemorySize, 79872);
        attr_done = true;
    }

    cudaMemsetAsync(hA, 0, (size_t)BB * HH * sizeof(float));
    cudaMemsetAsync(c,  0, (size_t)BB * HH * sizeof(float));

    permute_gates<<<((CC + NCLS) * 4 * HH + 255) / 256, 256>>>(lk, lkP, (CC + NCLS) * 4 * HH);
    permute_gates<<<(HH * 4 * HH + 255) / 256, 256>>>(lr, lrP, HH * 4 * HH);
    permute_gates<<<(4 * HH + 255) / 256, 256>>>(lb, lbP, 4 * HH);
    round_copy<<<(BB * TT * CC / 4 + 255) / 256, 256>>>(batch_H, bh32, BB * TT * CC / 4);
    half_copy<<<(BB * TT * CC / 4 + 255) / 256, 256>>>(batch_H, bh16, BB * TT * CC / 4);
    round_copy<<<(CC * HH / 4 + 255) / 256, 256>>>(Wi, wi32, CC * HH / 4);
    round_copy<<<(HH * HH / 4 + 255) / 256, 256>>>(Wh, wh32, HH * HH / 4);
    round_copy<<<(HH * NCLS / 4 + 255) / 256, 256>>>(Wgen, wg32, HH * NCLS / 4);

    // Hproj(fp16) = bh32 [B*T, C] @ wi32 [C, H]
    gemm_cp<2,8><<<dim3(HH / 128, (BB * TT) / 64), 128, 79872>>>(
        bh32, wi32, nullptr, nullptr, nullptr, (float*)hp16,
        BB * TT, HH, CC, CC, HH, HH, nullptr, nullptr, nullptr, 0);

    float* hbuf[2] = { hA, hB };
    for (int s = 0; s < NS; ++s) {
        float* hin  = hbuf[s & 1];
        float* hout = hbuf[(s + 1) & 1];
        gemm_cp<0,2><<<dim3(HH / 32, BB / 64), 128, 43008>>>(
            hin, wh32, nullptr, nullptr, bh, q,
            BB, HH, HH, HH, HH, HH, nullptr, nullptr, nullptr, 0);
        attn_kernel<<<BB, 256>>>(q, hp16, bh16, Ws, ctx);
        gemm_cp<1,8><<<dim3((4 * HH) / 128, BB / 64), 128, 79872>>>(
            ctx, lkP, hin, lrP, nullptr, hout,
            BB, 4 * HH, CC, CC, 4 * HH, 4 * HH, lkP, lbP, text, s);
    }

    // probs = hs [B*NS, H] @ wg32 [H, NC] + bgen   (BN=32, N=96 exact)
    gemm_cp<0,2><<<dim3(NCLS / 32, (BB * NS) / 64), 128, 43008>>>(
        hs, wg32, nullptr, nullptr, bgen, (float*)d_out,
        BB * NS, NCLS, HH, HH, NCLS, NCLS, nullptr, nullptr, nullptr, 0);
}

// round 13
// speedup vs baseline: 2.9197x; 1.3439x over previous
#include <cuda_runtime.h>
#include <cuda_bf16.h>
#include <cuda_fp16.h>
#include <cstdint>

// Problem constants
#define BB   512
#define TT   64
#define CC   512
#define HH   512
#define NCLS 96
#define NS   26

// ---------------- device scratch -------------------------------------------
__device__ __half g_hp16[(size_t)BB * TT * HH];   // fp16 Hproj
__device__ __half g_bh16[(size_t)BB * TT * CC];   // fp16 batch_H
__device__ __half g_wi16[(size_t)CC * HH];
__device__ __half g_wh16[(size_t)HH * HH];
__device__ __half g_wg16[(size_t)HH * NCLS];
__device__ __half g_lk16[(size_t)(CC + NCLS) * 4 * HH];  // permuted, fp16
__device__ __half g_lr16[(size_t)HH * 4 * HH];           // permuted, fp16
__device__ float  g_lbP [(size_t)4 * HH];                // permuted bias fp32
__device__ __half g_h16A[(size_t)BB * HH];               // h double buffer fp16
__device__ __half g_h16B[(size_t)BB * HH];
__device__ __half g_ctx16[(size_t)BB * CC];
__device__ __half g_hs16[(size_t)BB * NS * HH];
__device__ float  g_q  [(size_t)BB * HH];
__device__ float  g_c  [(size_t)BB * HH];

// ---------------- helpers ----------------------------------------------------
__device__ __forceinline__ float sigm(float x) { return 1.f / (1.f + __expf(-x)); }

__device__ __forceinline__ void mma16816(float* d, const uint32_t* a, const uint32_t* b) {
    asm volatile(
        "mma.sync.aligned.m16n8k16.row.col.f32.f16.f16.f32 "
        "{%0,%1,%2,%3}, {%4,%5,%6,%7}, {%8,%9}, {%0,%1,%2,%3};"
        : "+f"(d[0]), "+f"(d[1]), "+f"(d[2]), "+f"(d[3])
        : "r"(a[0]), "r"(a[1]), "r"(a[2]), "r"(a[3]),
          "r"(b[0]), "r"(b[1]));
}
__device__ __forceinline__ void ldsm_x4(uint32_t* r, uint32_t addr) {
    asm volatile("ldmatrix.sync.aligned.m8n8.x4.shared.b16 {%0,%1,%2,%3}, [%4];"
        : "=r"(r[0]), "=r"(r[1]), "=r"(r[2]), "=r"(r[3]) : "r"(addr));
}
__device__ __forceinline__ void ldsm_x4_t(uint32_t* r, uint32_t addr) {
    asm volatile("ldmatrix.sync.aligned.m8n8.x4.trans.shared.b16 {%0,%1,%2,%3}, [%4];"
        : "=r"(r[0]), "=r"(r[1]), "=r"(r[2]), "=r"(r[3]) : "r"(addr));
}

// ---------------- fp16 cp.async 3-stage GEMM --------------------------------
// Block tile 64 x (NT*16), BK=32 halves, 128 threads, 4 warps, warp 32 x (NT*8).
// A smem [64][PA=40] halves, B smem [32][PB=BN+8] halves (k-major rows).
// All fragment traffic via ldmatrix (A: x4 ; B: x4.trans), conflict-free pitches.
// MODE 0: fp32 C (+bias). MODE 1: fused LSTM gates (C = fp16 h_out).
// MODE 2: fp16 C. Requires M % 64 == 0 and N % BN == 0 (true for all call sites).
template<int MODE, int NT>
__global__ __launch_bounds__(128)
void gemm_h(const __half* __restrict__ A1, const __half* __restrict__ B1,
            const __half* __restrict__ A2, const __half* __restrict__ B2,
            const float* __restrict__ bias, float* __restrict__ C,
            int M, int N, int K, int lda, int ldb, int ldc,
            const __half* __restrict__ lk16, const float* __restrict__ lbP,
            const int* __restrict__ text, int step)
{
    constexpr int BN = NT * 16;
    constexpr int PA = 40;                 // halves
    constexpr int PB = BN + 8;             // halves
    constexpr int A_H = 64 * PA;           // 2560 halves
    constexpr int B_H = 32 * PB;
    constexpr int STAGE_BYTES = (A_H + B_H) * 2;
    constexpr int BCH = BN / 8;            // 16B chunks per B row

    extern __shared__ __half SMh[];
    const int tid = threadIdx.x;
    const int wid = tid >> 5, lane = tid & 31;
    const int warpM = wid >> 1, warpN = wid & 1;
    const int g = lane >> 2, t = lane & 3;
    const int m0 = blockIdx.y * 64, n0 = blockIdx.x * BN;
    const int kpt = K / 32;
    const int npass = (A2 != nullptr) ? 2 : 1;
    const int nk = kpt * npass;
    const uint32_t sbase = (uint32_t)__cvta_generic_to_shared(SMh);

    // ldmatrix per-lane tile-row selectors
    const int lr8 = lane & 7;
    const int selR = (lane >> 3) & 1;      // +8 rows (A) / +8 k (B)
    const int selC = (lane >> 4) & 1;      // +8 cols (A k / B n)

    float acc[2][NT][4];
#pragma unroll
    for (int i = 0; i < 2; ++i)
#pragma unroll
        for (int j = 0; j < NT; ++j)
#pragma unroll
            for (int k = 0; k < 4; ++k) acc[i][j][k] = 0.f;

    auto issue = [&](int kt) {
        if (kt < nk) {
            const int pass = kt / kpt;
            const int k0 = (kt - pass * kpt) * 32;
            const __half* __restrict__ A = pass ? A2 : A1;
            const __half* __restrict__ B = pass ? B2 : B1;
            const uint32_t ab = sbase + (uint32_t)(kt % 3) * STAGE_BYTES;
            const uint32_t bb = ab + A_H * 2;
#pragma unroll
            for (int i = 0; i < 2; ++i) {              // A: 256 16B chunks
                const int lin = tid + 128 * i;
                const int row = lin >> 2, q = lin & 3;
                const uint32_t d = ab + (uint32_t)(row * PA + q * 8) * 2u;
                const __half* s = A + (size_t)(m0 + row) * lda + k0 + q * 8;
                asm volatile("cp.async.cg.shared.global [%0], [%1], 16;"
                             :: "r"(d), "l"(s));
            }
#pragma unroll
            for (int i = 0; i < (32 * BCH) / 128; ++i) {   // B chunks
                const int lin = tid + 128 * i;
                const int kk = lin / BCH, q = lin % BCH;
                const uint32_t d = bb + (uint32_t)(kk * PB + q * 8) * 2u;
                const __half* s = B + (size_t)(k0 + kk) * ldb + n0 + q * 8;
                asm volatile("cp.async.cg.shared.global [%0], [%1], 16;"
                             :: "r"(d), "l"(s));
            }
        }
        asm volatile("cp.async.commit_group;" ::: "memory");
    };

    issue(0);
    issue(1);

    for (int kt = 0; kt < nk; ++kt) {
        asm volatile("cp.async.wait_group 1;" ::: "memory");
        __syncthreads();
        issue(kt + 2);

        const uint32_t ab = sbase + (uint32_t)(kt % 3) * STAGE_BYTES;
        const uint32_t bb = ab + A_H * 2;

        uint32_t fa[2][2][4], fb[2][NT][2];
        auto ldfrag = [&](int kb16, int slot) {
            const int kh = kb16 * 16;
#pragma unroll
            for (int mt = 0; mt < 2; ++mt) {
                const int row = warpM * 32 + mt * 16 + lr8 + selR * 8;
                const int col = kh + selC * 8;
                ldsm_x4(fa[slot][mt], ab + (uint32_t)(row * PA + col) * 2u);
            }
#pragma unroll
            for (int np = 0; np < NT / 2; ++np) {
                const int bk = kh + lr8 + selR * 8;
                const int bn = warpN * (NT * 8) + np * 16 + selC * 8;
                uint32_t q4[4];
                ldsm_x4_t(q4, bb + (uint32_t)(bk * PB + bn) * 2u);
                fb[slot][2 * np][0] = q4[0]; fb[slot][2 * np][1] = q4[1];
                fb[slot][2 * np + 1][0] = q4[2]; fb[slot][2 * np + 1][1] = q4[3];
            }
        };

        ldfrag(0, 0);
        ldfrag(1, 1);
#pragma unroll
        for (int s = 0; s < 2; ++s)
#pragma unroll
            for (int mt = 0; mt < 2; ++mt)
#pragma unroll
                for (int nt = 0; nt < NT; ++nt)
                    mma16816(acc[mt][nt], fa[s][mt], fb[s][nt]);
    }

    if (MODE == 0) {
#pragma unroll
        for (int mt = 0; mt < 2; ++mt) {
#pragma unroll
            for (int nt = 0; nt < NT; ++nt) {
                const int col = n0 + warpN * (NT * 8) + nt * 8 + 2 * t;
                const int row = m0 + warpM * 32 + mt * 16 + g;
                float b0 = bias ? bias[col] : 0.f;
                float b1 = bias ? bias[col + 1] : 0.f;
                *(float2*)(C + (size_t)row * ldc + col) =
                    make_float2(acc[mt][nt][0] + b0, acc[mt][nt][1] + b1);
                *(float2*)(C + (size_t)(row + 8) * ldc + col) =
                    make_float2(acc[mt][nt][2] + b0, acc[mt][nt][3] + b1);
            }
        }
    } else if (MODE == 2) {
        __half* C16 = (__half*)C;
#pragma unroll
        for (int mt = 0; mt < 2; ++mt) {
#pragma unroll
            for (int nt = 0; nt < NT; ++nt) {
                const int col = n0 + warpN * (NT * 8) + nt * 8 + 2 * t;
                const int row = m0 + warpM * 32 + mt * 16 + g;
                *(__half2*)(C16 + (size_t)row * ldc + col) =
                    __floats2half2_rn(acc[mt][nt][0], acc[mt][nt][1]);
                *(__half2*)(C16 + (size_t)(row + 8) * ldc + col) =
                    __floats2half2_rn(acc[mt][nt][2], acc[mt][nt][3]);
            }
        }
    } else {
        // fused LSTM gates; C = fp16 h_out (double-buffered).
        __syncthreads();
        float* zs = (float*)SMh;              // [64][BN+2]
        constexpr int ZP = BN + 2;
#pragma unroll
        for (int mt = 0; mt < 2; ++mt) {
#pragma unroll
            for (int nt = 0; nt < NT; ++nt) {
                const int c0 = warpN * (NT * 8) + nt * 8 + 2 * t;
                const int r0 = warpM * 32 + mt * 16 + g;
                zs[r0 * ZP + c0]           = acc[mt][nt][0];
                zs[r0 * ZP + c0 + 1]       = acc[mt][nt][1];
                zs[(r0 + 8) * ZP + c0]     = acc[mt][nt][2];
                zs[(r0 + 8) * ZP + c0 + 1] = acc[mt][nt][3];
            }
        }
        __syncthreads();
        __half* hout = (__half*)C;
        const int j0 = n0 >> 2;
        constexpr int NJ = BN / 4;
#pragma unroll
        for (int p = tid; p < 64 * NJ; p += 128) {
            const int r = p & 63, jj = p >> 6;
            const int b = m0 + r, j = j0 + jj;
            const int ch = text[b * NS + step];
            const float* zrow = zs + r * ZP + jj * 4;
            const __half2* ohp =
                (const __half2*)(lk16 + (size_t)(CC + ch) * (4 * HH) + 4 * j);
            float2 o01 = __half22float2(ohp[0]);
            float2 o23 = __half22float2(ohp[1]);
            float4 bb4 = *(const float4*)(lbP + 4 * j);
            float zi = zrow[0] + o01.x + bb4.x;
            float zf = zrow[1] + o01.y + bb4.y;
            float zg = zrow[2] + o23.x + bb4.z;
            float zo = zrow[3] + o23.y + bb4.w;
            const int ci = b * HH + j;
            float cn = sigm(zf) * g_c[ci] + sigm(zi) * tanhf(zg);
            float hn = sigm(zo) * tanhf(cn);
            __half hh = __float2half_rn(hn);
            g_c[ci] = cn;
            hout[ci] = hh;
            g_hs16[((size_t)b * NS + step) * HH + j] = hh;
        }
    }
}

// ---------------- prep kernels ------------------------------------------------
__global__ __launch_bounds__(256)
void permute_gates_h(const float* __restrict__ in, __half* __restrict__ out, int total)
{
    int idx = blockIdx.x * 256 + threadIdx.x;
    if (idx >= total) return;
    int row = idx >> 11, oc = idx & 2047;
    int j = oc >> 2, gate = oc & 3;
    out[idx] = __float2half_rn(in[(size_t)row * 2048 + gate * HH + j]);
}
__global__ __launch_bounds__(256)
void permute_bias(const float* __restrict__ in, float* __restrict__ out)
{
    int idx = blockIdx.x * 256 + threadIdx.x;
    if (idx >= 4 * HH) return;
    int j = idx >> 2, gate = idx & 3;
    out[idx] = in[gate * HH + j];
}
__global__ __launch_bounds__(256)
void half_copy(const float* __restrict__ in, __half* __restrict__ out, int n4)
{
    int i = blockIdx.x * 256 + threadIdx.x;
    if (i >= n4) return;
    float4 v = ((const float4*)in)[i];
    ((__half2*)out)[2 * i]     = __floats2half2_rn(v.x, v.y);
    ((__half2*)out)[2 * i + 1] = __floats2half2_rn(v.z, v.w);
}

// ---------------- fused attention (fp16 Hproj + batch_H, fp16 ctx out) -------
__global__ __launch_bounds__(256)
void attn_kernel(const float* __restrict__ q,
                 const __half* __restrict__ hp16,
                 const __half* __restrict__ bh16,
                 const float* __restrict__ Ws,
                 __half* __restrict__ ctx16)
{
    const int b = blockIdx.x;
    __shared__ float qs[HH];
    __shared__ float ws[HH];
    __shared__ float e[TT];

    const int tid = threadIdx.x;
    for (int i = tid; i < HH; i += 256) { qs[i] = q[(size_t)b * HH + i]; ws[i] = Ws[i]; }
    __syncthreads();

    const int warp = tid >> 5, lane = tid & 31;
    for (int t = warp; t < TT; t += 8) {
        const __half2* __restrict__ hp =
            (const __half2*)(hp16 + ((size_t)b * TT + t) * HH);
        float p = 0.f;
#pragma unroll
        for (int j = 0; j < 8; ++j) {
            const int idx = lane + 32 * j;
            float2 f = __half22float2(hp[idx]);
            float2 qv = *(const float2*)&qs[2 * idx];
            float2 wv = *(const float2*)&ws[2 * idx];
            p += tanhf(f.x + qv.x) * wv.x + tanhf(f.y + qv.y) * wv.y;
        }
#pragma unroll
        for (int o = 16; o; o >>= 1) p += __shfl_xor_sync(0xffffffffu, p, o);
        if (lane == 0) e[t] = p;
    }
    __syncthreads();

    if (warp == 0) {
        float v0 = e[lane], v1 = e[lane + 32];
        float m = fmaxf(v0, v1);
#pragma unroll
        for (int o = 16; o; o >>= 1) m = fmaxf(m, __shfl_xor_sync(0xffffffffu, m, o));
        float x0 = __expf(v0 - m), x1 = __expf(v1 - m);
        float s = x0 + x1;
#pragma unroll
        for (int o = 16; o; o >>= 1) s += __shfl_xor_sync(0xffffffffu, s, o);
        float inv = 1.f / s;
        e[lane] = x0 * inv;
        e[lane + 32] = x1 * inv;
    }
    __syncthreads();

    {
        const __half2* __restrict__ bp =
            (const __half2*)(bh16 + (size_t)b * TT * CC);
        float2 acc = make_float2(0.f, 0.f);
#pragma unroll 8
        for (int t = 0; t < TT; ++t) {
            float2 f = __half22float2(bp[t * (CC / 2) + tid]);
            float a = e[t];
            acc.x = fmaf(a, f.x, acc.x);
            acc.y = fmaf(a, f.y, acc.y);
        }
        ((__half2*)ctx16)[(size_t)b * (CC / 2) + tid] =
            __floats2half2_rn(acc.x, acc.y);
    }
}

// ---------------- launch -----------------------------------------------------
extern "C" void kernel_launch(void* const* d_in, const int* in_sizes, int n_in,
                              void* d_out, int out_size)
{
    int off = 0;
    if (n_in >= 3 && in_sizes[2] == 1) off = 1;
    const float* batch_H = (const float*)d_in[0];
    const int*   text    = (const int*)  d_in[1];
    const float* Wi      = (const float*)d_in[2 + off];
    const float* Wh      = (const float*)d_in[3 + off];
    const float* bh      = (const float*)d_in[4 + off];
    const float* Ws      = (const float*)d_in[5 + off];
    const float* lk      = (const float*)d_in[6 + off];
    const float* lr      = (const float*)d_in[7 + off];
    const float* lb      = (const float*)d_in[8 + off];
    const float* Wgen    = (const float*)d_in[9 + off];
    const float* bgen    = (const float*)d_in[10 + off];

    __half *hp16, *bh16, *wi16, *wh16, *wg16, *lk16, *lr16, *hA, *hB, *ctx16, *hs16;
    float *lbP, *q, *c;
    cudaGetSymbolAddress((void**)&hp16, g_hp16);
    cudaGetSymbolAddress((void**)&bh16, g_bh16);
    cudaGetSymbolAddress((void**)&wi16, g_wi16);
    cudaGetSymbolAddress((void**)&wh16, g_wh16);
    cudaGetSymbolAddress((void**)&wg16, g_wg16);
    cudaGetSymbolAddress((void**)&lk16, g_lk16);
    cudaGetSymbolAddress((void**)&lr16, g_lr16);
    cudaGetSymbolAddress((void**)&lbP,  g_lbP);
    cudaGetSymbolAddress((void**)&hA,   g_h16A);
    cudaGetSymbolAddress((void**)&hB,   g_h16B);
    cudaGetSymbolAddress((void**)&ctx16,g_ctx16);
    cudaGetSymbolAddress((void**)&hs16, g_hs16);
    cudaGetSymbolAddress((void**)&q,    g_q);
    cudaGetSymbolAddress((void**)&c,    g_c);

    cudaMemsetAsync(hA, 0, (size_t)BB * HH * sizeof(__half));
    cudaMemsetAsync(c,  0, (size_t)BB * HH * sizeof(float));

    // prep: fp16 conversions + gate permutation
    half_copy<<<(BB * TT * CC / 4 + 255) / 256, 256>>>(batch_H, bh16, BB * TT * CC / 4);
    half_copy<<<(CC * HH / 4 + 255) / 256, 256>>>(Wi, wi16, CC * HH / 4);
    half_copy<<<(HH * HH / 4 + 255) / 256, 256>>>(Wh, wh16, HH * HH / 4);
    half_copy<<<(HH * NCLS / 4 + 255) / 256, 256>>>(Wgen, wg16, HH * NCLS / 4);
    permute_gates_h<<<((CC + NCLS) * 4 * HH + 255) / 256, 256>>>(lk, lk16, (CC + NCLS) * 4 * HH);
    permute_gates_h<<<(HH * 4 * HH + 255) / 256, 256>>>(lr, lr16, HH * 4 * HH);
    permute_bias<<<(4 * HH + 255) / 256, 256>>>(lb, lbP);

    // smem: NT=2 -> ((2560+32*40)*2)*3 = 23040 ; NT=4 -> ((2560+32*72)*2)*3 = 29184
    // Hproj(fp16) = bh16 [B*T, C] @ wi16 [C, H]   (BN=64, grid 4096)
    gemm_h<2,4><<<dim3(HH / 64, (BB * TT) / 64), 128, 29184>>>(
        bh16, wi16, nullptr, nullptr, nullptr, (float*)hp16,
        BB * TT, HH, CC, CC, HH, HH, nullptr, nullptr, nullptr, 0);

    __half* hbuf[2] = { hA, hB };
    for (int s = 0; s < NS; ++s) {
        __half* hin  = hbuf[s & 1];
        __half* hout = hbuf[(s + 1) & 1];
        // q = h @ Wh + bh   (BN=32, grid 128, fp32 out)
        gemm_h<0,2><<<dim3(HH / 32, BB / 64), 128, 23040>>>(
            hin, wh16, nullptr, nullptr, bh, q,
            BB, HH, HH, HH, HH, HH, nullptr, nullptr, nullptr, 0);
        attn_kernel<<<BB, 256>>>(q, hp16, bh16, Ws, ctx16);
        // fused: z = ctx @ lk16 + h @ lr16 ; gates  (BN=64, grid 256)
        gemm_h<1,4><<<dim3((4 * HH) / 64, BB / 64), 128, 29184>>>(
            ctx16, lk16, hin, lr16, nullptr, (float*)hout,
            BB, 4 * HH, CC, CC, 4 * HH, 4 * HH, lk16, lbP, text, s);
    }

    // probs = hs16 [B*NS, H] @ wg16 [H, NC] + bgen  (BN=32, grid 624, fp32 out)
    gemm_h<0,2><<<dim3(NCLS / 32, (BB * NS) / 64), 128, 23040>>>(
        hs16, wg16, nullptr, nullptr, bgen, (float*)d_out,
        BB * NS, NCLS, HH, HH, NCLS, NCLS, nullptr, nullptr, nullptr, 0);
}

// round 14
// speedup vs baseline: 3.1648x; 1.0840x over previous
#include <cuda_runtime.h>
#include <cuda_bf16.h>
#include <cuda_fp16.h>
#include <cstdint>

// Problem constants
#define BB   512
#define TT   64
#define CC   512
#define HH   512
#define NCLS 96
#define NS   26

// ---------------- device scratch -------------------------------------------
__device__ __half g_hp16[(size_t)BB * TT * HH];   // fp16 Hproj
__device__ __half g_bh16[(size_t)BB * TT * CC];   // fp16 batch_H
__device__ __half g_wi16[(size_t)CC * HH];
__device__ __half g_wg16[(size_t)HH * NCLS];
__device__ __half g_cat16[(size_t)HH * 2560];            // [Wh | lrP] fp16
__device__ __half g_lk16[(size_t)(CC + NCLS) * 4 * HH];  // permuted, fp16
__device__ float  g_lbP [(size_t)4 * HH];                // permuted bias fp32
__device__ float  g_qz  [(size_t)BB * 2560];             // [q | zh] fp32
__device__ __half g_h16A[(size_t)BB * HH];               // h double buffer fp16
__device__ __half g_h16B[(size_t)BB * HH];
__device__ __half g_ctx16[(size_t)BB * CC];
__device__ __half g_hs16[(size_t)BB * NS * HH];
__device__ float  g_c  [(size_t)BB * HH];

// ---------------- helpers ----------------------------------------------------
__device__ __forceinline__ float sigm(float x) { return 1.f / (1.f + __expf(-x)); }
__device__ __forceinline__ float tanha(float x) {
    float y;
    asm("tanh.approx.f32 %0, %1;" : "=f"(y) : "f"(x));
    return y;
}
__device__ __forceinline__ void mma16816(float* d, const uint32_t* a, const uint32_t* b) {
    asm volatile(
        "mma.sync.aligned.m16n8k16.row.col.f32.f16.f16.f32 "
        "{%0,%1,%2,%3}, {%4,%5,%6,%7}, {%8,%9}, {%0,%1,%2,%3};"
        : "+f"(d[0]), "+f"(d[1]), "+f"(d[2]), "+f"(d[3])
        : "r"(a[0]), "r"(a[1]), "r"(a[2]), "r"(a[3]),
          "r"(b[0]), "r"(b[1]));
}
__device__ __forceinline__ void ldsm_x4(uint32_t* r, uint32_t addr) {
    asm volatile("ldmatrix.sync.aligned.m8n8.x4.shared.b16 {%0,%1,%2,%3}, [%4];"
        : "=r"(r[0]), "=r"(r[1]), "=r"(r[2]), "=r"(r[3]) : "r"(addr));
}
__device__ __forceinline__ void ldsm_x4_t(uint32_t* r, uint32_t addr) {
    asm volatile("ldmatrix.sync.aligned.m8n8.x4.trans.shared.b16 {%0,%1,%2,%3}, [%4];"
        : "=r"(r[0]), "=r"(r[1]), "=r"(r[2]), "=r"(r[3]) : "r"(addr));
}

// ---------------- fp16 cp.async 3-stage GEMM --------------------------------
// Block tile 64 x (NT*16), BK=32 halves, 128 threads, 4 warps, warp 32 x (NT*8).
// MODE 0: fp32 C (+bias). MODE 1: z=ctx@lk single-pass + zh addend + gates.
// MODE 2: fp16 C. Requires M%64==0, N%BN==0.
template<int MODE, int NT>
__global__ __launch_bounds__(128)
void gemm_h(const __half* __restrict__ A1, const __half* __restrict__ B1,
            const __half* __restrict__ A2, const __half* __restrict__ B2,
            const float* __restrict__ bias, float* __restrict__ C,
            int M, int N, int K, int lda, int ldb, int ldc,
            const __half* __restrict__ lk16, const float* __restrict__ lbP,
            const int* __restrict__ text, int step,
            const float* __restrict__ zhp)
{
    constexpr int BN = NT * 16;
    constexpr int PA = 40;
    constexpr int PB = BN + 8;
    constexpr int A_H = 64 * PA;
    constexpr int B_H = 32 * PB;
    constexpr int STAGE_BYTES = (A_H + B_H) * 2;
    constexpr int BCH = BN / 8;

    extern __shared__ __half SMh[];
    const int tid = threadIdx.x;
    const int wid = tid >> 5, lane = tid & 31;
    const int warpM = wid >> 1, warpN = wid & 1;
    const int g = lane >> 2, t = lane & 3;
    const int m0 = blockIdx.y * 64, n0 = blockIdx.x * BN;
    const int kpt = K / 32;
    const int npass = (A2 != nullptr) ? 2 : 1;
    const int nk = kpt * npass;
    const uint32_t sbase = (uint32_t)__cvta_generic_to_shared(SMh);

    const int lr8 = lane & 7;
    const int selR = (lane >> 3) & 1;
    const int selC = (lane >> 4) & 1;

    float acc[2][NT][4];
#pragma unroll
    for (int i = 0; i < 2; ++i)
#pragma unroll
        for (int j = 0; j < NT; ++j)
#pragma unroll
            for (int k = 0; k < 4; ++k) acc[i][j][k] = 0.f;

    auto issue = [&](int kt) {
        if (kt < nk) {
            const int pass = kt / kpt;
            const int k0 = (kt - pass * kpt) * 32;
            const __half* __restrict__ A = pass ? A2 : A1;
            const __half* __restrict__ B = pass ? B2 : B1;
            const uint32_t ab = sbase + (uint32_t)(kt % 3) * STAGE_BYTES;
            const uint32_t bb = ab + A_H * 2;
#pragma unroll
            for (int i = 0; i < 2; ++i) {
                const int lin = tid + 128 * i;
                const int row = lin >> 2, q = lin & 3;
                const uint32_t d = ab + (uint32_t)(row * PA + q * 8) * 2u;
                const __half* s = A + (size_t)(m0 + row) * lda + k0 + q * 8;
                asm volatile("cp.async.cg.shared.global [%0], [%1], 16;"
                             :: "r"(d), "l"(s));
            }
#pragma unroll
            for (int i = 0; i < (32 * BCH) / 128; ++i) {
                const int lin = tid + 128 * i;
                const int kk = lin / BCH, q = lin % BCH;
                const uint32_t d = bb + (uint32_t)(kk * PB + q * 8) * 2u;
                const __half* s = B + (size_t)(k0 + kk) * ldb + n0 + q * 8;
                asm volatile("cp.async.cg.shared.global [%0], [%1], 16;"
                             :: "r"(d), "l"(s));
            }
        }
        asm volatile("cp.async.commit_group;" ::: "memory");
    };

    issue(0);
    issue(1);

    for (int kt = 0; kt < nk; ++kt) {
        asm volatile("cp.async.wait_group 1;" ::: "memory");
        __syncthreads();
        issue(kt + 2);

        const uint32_t ab = sbase + (uint32_t)(kt % 3) * STAGE_BYTES;
        const uint32_t bb = ab + A_H * 2;

        uint32_t fa[2][2][4], fb[2][NT][2];
        auto ldfrag = [&](int kb16, int slot) {
            const int kh = kb16 * 16;
#pragma unroll
            for (int mt = 0; mt < 2; ++mt) {
                const int row = warpM * 32 + mt * 16 + lr8 + selR * 8;
                const int col = kh + selC * 8;
                ldsm_x4(fa[slot][mt], ab + (uint32_t)(row * PA + col) * 2u);
            }
#pragma unroll
            for (int np = 0; np < NT / 2; ++np) {
                const int bk = kh + lr8 + selR * 8;
                const int bn = warpN * (NT * 8) + np * 16 + selC * 8;
                uint32_t q4[4];
                ldsm_x4_t(q4, bb + (uint32_t)(bk * PB + bn) * 2u);
                fb[slot][2 * np][0] = q4[0]; fb[slot][2 * np][1] = q4[1];
                fb[slot][2 * np + 1][0] = q4[2]; fb[slot][2 * np + 1][1] = q4[3];
            }
        };

        ldfrag(0, 0);
        ldfrag(1, 1);
#pragma unroll
        for (int s = 0; s < 2; ++s)
#pragma unroll
            for (int mt = 0; mt < 2; ++mt)
#pragma unroll
                for (int nt = 0; nt < NT; ++nt)
                    mma16816(acc[mt][nt], fa[s][mt], fb[s][nt]);
    }

    if (MODE == 0) {
#pragma unroll
        for (int mt = 0; mt < 2; ++mt) {
#pragma unroll
            for (int nt = 0; nt < NT; ++nt) {
                const int col = n0 + warpN * (NT * 8) + nt * 8 + 2 * t;
                const int row = m0 + warpM * 32 + mt * 16 + g;
                float b0 = bias ? bias[col] : 0.f;
                float b1 = bias ? bias[col + 1] : 0.f;
                *(float2*)(C + (size_t)row * ldc + col) =
                    make_float2(acc[mt][nt][0] + b0, acc[mt][nt][1] + b1);
                *(float2*)(C + (size_t)(row + 8) * ldc + col) =
                    make_float2(acc[mt][nt][2] + b0, acc[mt][nt][3] + b1);
            }
        }
    } else if (MODE == 2) {
        __half* C16 = (__half*)C;
#pragma unroll
        for (int mt = 0; mt < 2; ++mt) {
#pragma unroll
            for (int nt = 0; nt < NT; ++nt) {
                const int col = n0 + warpN * (NT * 8) + nt * 8 + 2 * t;
                const int row = m0 + warpM * 32 + mt * 16 + g;
                *(__half2*)(C16 + (size_t)row * ldc + col) =
                    __floats2half2_rn(acc[mt][nt][0], acc[mt][nt][1]);
                *(__half2*)(C16 + (size_t)(row + 8) * ldc + col) =
                    __floats2half2_rn(acc[mt][nt][2], acc[mt][nt][3]);
            }
        }
    } else {
        // fused LSTM gates; z = acc + zh + onehot + bias; C = fp16 h_out.
        __syncthreads();
        float* zs = (float*)SMh;
        constexpr int ZP = BN + 2;
#pragma unroll
        for (int mt = 0; mt < 2; ++mt) {
#pragma unroll
            for (int nt = 0; nt < NT; ++nt) {
                const int c0 = warpN * (NT * 8) + nt * 8 + 2 * t;
                const int r0 = warpM * 32 + mt * 16 + g;
                zs[r0 * ZP + c0]           = acc[mt][nt][0];
                zs[r0 * ZP + c0 + 1]       = acc[mt][nt][1];
                zs[(r0 + 8) * ZP + c0]     = acc[mt][nt][2];
                zs[(r0 + 8) * ZP + c0 + 1] = acc[mt][nt][3];
            }
        }
        __syncthreads();
        __half* hout = (__half*)C;
        const int j0 = n0 >> 2;
        constexpr int NJ = BN / 4;
#pragma unroll
        for (int p = tid; p < 64 * NJ; p += 128) {
            const int r = p & 63, jj = p >> 6;
            const int b = m0 + r, j = j0 + jj;
            const int ch = text[b * NS + step];
            const float* zrow = zs + r * ZP + jj * 4;
            const __half2* ohp =
                (const __half2*)(lk16 + (size_t)(CC + ch) * (4 * HH) + 4 * j);
            float2 o01 = __half22float2(ohp[0]);
            float2 o23 = __half22float2(ohp[1]);
            float4 bb4 = *(const float4*)(lbP + 4 * j);
            float4 zh4 = *(const float4*)(zhp + (size_t)b * 2560 + 512 + 4 * j);
            float zi = zrow[0] + zh4.x + o01.x + bb4.x;
            float zf = zrow[1] + zh4.y + o01.y + bb4.y;
            float zg = zrow[2] + zh4.z + o23.x + bb4.z;
            float zo = zrow[3] + zh4.w + o23.y + bb4.w;
            const int ci = b * HH + j;
            float cn = sigm(zf) * g_c[ci] + sigm(zi) * tanhf(zg);
            float hn = sigm(zo) * tanhf(cn);
            __half hh = __float2half_rn(hn);
            g_c[ci] = cn;
            hout[ci] = hh;
            g_hs16[((size_t)b * NS + step) * HH + j] = hh;
        }
    }
}

// ---------------- prep kernels ------------------------------------------------
__global__ __launch_bounds__(256)
void permute_gates_h(const float* __restrict__ in, __half* __restrict__ out, int total)
{
    int idx = blockIdx.x * 256 + threadIdx.x;
    if (idx >= total) return;
    int row = idx >> 11, oc = idx & 2047;
    int j = oc >> 2, gate = oc & 3;
    out[idx] = __float2half_rn(in[(size_t)row * 2048 + gate * HH + j]);
}
__global__ __launch_bounds__(256)
void permute_bias(const float* __restrict__ in, float* __restrict__ out)
{
    int idx = blockIdx.x * 256 + threadIdx.x;
    if (idx >= 4 * HH) return;
    int j = idx >> 2, gate = idx & 3;
    out[idx] = in[gate * HH + j];
}
// catW[k][0:512] = Wh[k][:], catW[k][512+4j+g] = lr[k][g*512+j]
__global__ __launch_bounds__(256)
void cat_weights(const float* __restrict__ Wh, const float* __restrict__ lr,
                 __half* __restrict__ out)
{
    int idx = blockIdx.x * 256 + threadIdx.x;
    if (idx >= HH * 2560) return;
    int k = idx / 2560, c = idx % 2560;
    float v;
    if (c < HH) v = Wh[(size_t)k * HH + c];
    else {
        int cc = c - HH, j = cc >> 2, gate = cc & 3;
        v = lr[(size_t)k * 2048 + gate * HH + j];
    }
    out[idx] = __float2half_rn(v);
}
__global__ __launch_bounds__(256)
void half_copy(const float* __restrict__ in, __half* __restrict__ out, int n4)
{
    int i = blockIdx.x * 256 + threadIdx.x;
    if (i >= n4) return;
    float4 v = ((const float4*)in)[i];
    ((__half2*)out)[2 * i]     = __floats2half2_rn(v.x, v.y);
    ((__half2*)out)[2 * i + 1] = __floats2half2_rn(v.z, v.w);
}

// ---------------- fused attention (tanh.approx e-phase) ----------------------
__global__ __launch_bounds__(256)
void attn_kernel(const float* __restrict__ qz,     // [B][2560], q in cols 0:512
                 const float* __restrict__ bh,
                 const __half* __restrict__ hp16,
                 const __half* __restrict__ bh16,
                 const float* __restrict__ Ws,
                 __half* __restrict__ ctx16)
{
    const int b = blockIdx.x;
    __shared__ float qs[HH];
    __shared__ float ws[HH];
    __shared__ float e[TT];

    const int tid = threadIdx.x;
    for (int i = tid; i < HH; i += 256) {
        qs[i] = qz[(size_t)b * 2560 + i] + bh[i];
        ws[i] = Ws[i];
    }
    __syncthreads();

    const int warp = tid >> 5, lane = tid & 31;
    for (int t = warp; t < TT; t += 8) {
        const __half2* __restrict__ hp =
            (const __half2*)(hp16 + ((size_t)b * TT + t) * HH);
        float p = 0.f;
#pragma unroll
        for (int j = 0; j < 8; ++j) {
            const int idx = lane + 32 * j;
            float2 f = __half22float2(hp[idx]);
            float2 qv = *(const float2*)&qs[2 * idx];
            float2 wv = *(const float2*)&ws[2 * idx];
            p += tanha(f.x + qv.x) * wv.x + tanha(f.y + qv.y) * wv.y;
        }
#pragma unroll
        for (int o = 16; o; o >>= 1) p += __shfl_xor_sync(0xffffffffu, p, o);
        if (lane == 0) e[t] = p;
    }
    __syncthreads();

    if (warp == 0) {
        float v0 = e[lane], v1 = e[lane + 32];
        float m = fmaxf(v0, v1);
#pragma unroll
        for (int o = 16; o; o >>= 1) m = fmaxf(m, __shfl_xor_sync(0xffffffffu, m, o));
        float x0 = __expf(v0 - m), x1 = __expf(v1 - m);
        float s = x0 + x1;
#pragma unroll
        for (int o = 16; o; o >>= 1) s += __shfl_xor_sync(0xffffffffu, s, o);
        float inv = 1.f / s;
        e[lane] = x0 * inv;
        e[lane + 32] = x1 * inv;
    }
    __syncthreads();

    {
        const __half2* __restrict__ bp =
            (const __half2*)(bh16 + (size_t)b * TT * CC);
        float2 acc = make_float2(0.f, 0.f);
#pragma unroll 8
        for (int t = 0; t < TT; ++t) {
            float2 f = __half22float2(bp[t * (CC / 2) + tid]);
            float a = e[t];
            acc.x = fmaf(a, f.x, acc.x);
            acc.y = fmaf(a, f.y, acc.y);
        }
        ((__half2*)ctx16)[(size_t)b * (CC / 2) + tid] =
            __floats2half2_rn(acc.x, acc.y);
    }
}

// ---------------- launch -----------------------------------------------------
extern "C" void kernel_launch(void* const* d_in, const int* in_sizes, int n_in,
                              void* d_out, int out_size)
{
    int off = 0;
    if (n_in >= 3 && in_sizes[2] == 1) off = 1;
    const float* batch_H = (const float*)d_in[0];
    const int*   text    = (const int*)  d_in[1];
    const float* Wi      = (const float*)d_in[2 + off];
    const float* Wh      = (const float*)d_in[3 + off];
    const float* bh      = (const float*)d_in[4 + off];
    const float* Ws      = (const float*)d_in[5 + off];
    const float* lk      = (const float*)d_in[6 + off];
    const float* lr      = (const float*)d_in[7 + off];
    const float* lb      = (const float*)d_in[8 + off];
    const float* Wgen    = (const float*)d_in[9 + off];
    const float* bgen    = (const float*)d_in[10 + off];

    __half *hp16, *bh16, *wi16, *wg16, *cat16, *lk16, *hA, *hB, *ctx16, *hs16;
    float *lbP, *qz, *c;
    cudaGetSymbolAddress((void**)&hp16, g_hp16);
    cudaGetSymbolAddress((void**)&bh16, g_bh16);
    cudaGetSymbolAddress((void**)&wi16, g_wi16);
    cudaGetSymbolAddress((void**)&wg16, g_wg16);
    cudaGetSymbolAddress((void**)&cat16,g_cat16);
    cudaGetSymbolAddress((void**)&lk16, g_lk16);
    cudaGetSymbolAddress((void**)&lbP,  g_lbP);
    cudaGetSymbolAddress((void**)&qz,   g_qz);
    cudaGetSymbolAddress((void**)&hA,   g_h16A);
    cudaGetSymbolAddress((void**)&hB,   g_h16B);
    cudaGetSymbolAddress((void**)&ctx16,g_ctx16);
    cudaGetSymbolAddress((void**)&hs16, g_hs16);
    cudaGetSymbolAddress((void**)&c,    g_c);

    cudaMemsetAsync(hA, 0, (size_t)BB * HH * sizeof(__half));
    cudaMemsetAsync(c,  0, (size_t)BB * HH * sizeof(float));

    // prep
    half_copy<<<(BB * TT * CC / 4 + 255) / 256, 256>>>(batch_H, bh16, BB * TT * CC / 4);
    half_copy<<<(CC * HH / 4 + 255) / 256, 256>>>(Wi, wi16, CC * HH / 4);
    half_copy<<<(HH * NCLS / 4 + 255) / 256, 256>>>(Wgen, wg16, HH * NCLS / 4);
    cat_weights<<<(HH * 2560 + 255) / 256, 256>>>(Wh, lr, cat16);
    permute_gates_h<<<((CC + NCLS) * 4 * HH + 255) / 256, 256>>>(lk, lk16, (CC + NCLS) * 4 * HH);
    permute_bias<<<(4 * HH + 255) / 256, 256>>>(lb, lbP);

    // smem: NT=2 -> 23040 ; NT=4 -> 29184 ; NT=8 -> ((2560+32*136)*2)*3 = 41472
    // Hproj(fp16) = bh16 [B*T, C] @ wi16 [C, H]   (BN=128, grid 2048)
    gemm_h<2,8><<<dim3(HH / 128, (BB * TT) / 64), 128, 41472>>>(
        bh16, wi16, nullptr, nullptr, nullptr, (float*)hp16,
        BB * TT, HH, CC, CC, HH, HH, nullptr, nullptr, nullptr, 0, nullptr);

    __half* hbuf[2] = { hA, hB };
    for (int s = 0; s < NS; ++s) {
        __half* hin  = hbuf[s & 1];
        __half* hout = hbuf[(s + 1) & 1];
        // [q | zh] = h @ cat16   (N=2560, BN=64, grid 320, fp32 out)
        gemm_h<0,4><<<dim3(2560 / 64, BB / 64), 128, 29184>>>(
            hin, cat16, nullptr, nullptr, nullptr, qz,
            BB, 2560, HH, HH, 2560, 2560, nullptr, nullptr, nullptr, 0, nullptr);
        attn_kernel<<<BB, 256>>>(qz, bh, hp16, bh16, Ws, ctx16);
        // z = ctx @ lk16 (K=512 single pass) + zh + gates  (BN=64, grid 256)
        gemm_h<1,4><<<dim3((4 * HH) / 64, BB / 64), 128, 29184>>>(
            ctx16, lk16, nullptr, nullptr, nullptr, (float*)hout,
            BB, 4 * HH, CC, CC, 4 * HH, 4 * HH, lk16, lbP, text, s, qz);
    }

    // probs = hs16 [B*NS, H] @ wg16 [H, NC] + bgen  (BN=32, grid 624, fp32 out)
    gemm_h<0,2><<<dim3(NCLS / 32, (BB * NS) / 64), 128, 23040>>>(
        hs16, wg16, nullptr, nullptr, bgen, (float*)d_out,
        BB * NS, NCLS, HH, HH, NCLS, NCLS, nullptr, nullptr, nullptr, 0, nullptr);
}

// round 16
// speedup vs baseline: 3.2594x; 1.0299x over previous
#include <cuda_runtime.h>
#include <cuda_bf16.h>
#include <cuda_fp16.h>
#include <cstdint>

// Problem constants
#define BB   512
#define TT   64
#define CC   512
#define HH   512
#define NCLS 96
#define NS   26

// ---------------- device scratch -------------------------------------------
__device__ __half g_hp16[(size_t)BB * TT * HH];   // fp16 Hproj
__device__ __half g_bh16[(size_t)BB * TT * CC];   // fp16 batch_H
__device__ __half g_wi16[(size_t)CC * HH];
__device__ __half g_wg16[(size_t)HH * NCLS];
__device__ __half g_wh16[(size_t)HH * HH];
__device__ __half g_lr16[(size_t)HH * 4 * HH];           // permuted, fp16
__device__ __half g_lk16[(size_t)(CC + NCLS) * 4 * HH];  // permuted, fp16
__device__ float  g_lbP [(size_t)4 * HH];                // permuted bias fp32
__device__ float  g_q   [(size_t)BB * HH];               // q fp32
__device__ float  g_zh  [(size_t)BB * 4 * HH];           // h@lr fp32
__device__ __half g_h16A[(size_t)BB * HH];               // h double buffer fp16
__device__ __half g_h16B[(size_t)BB * HH];
__device__ __half g_ctx16[(size_t)BB * CC];
__device__ __half g_hs16[(size_t)BB * NS * HH];
__device__ float  g_c  [(size_t)BB * HH];

// ---------------- helpers ----------------------------------------------------
__device__ __forceinline__ float sigm(float x) { return 1.f / (1.f + __expf(-x)); }
__device__ __forceinline__ float tanha(float x) {
    float y;
    asm("tanh.approx.f32 %0, %1;" : "=f"(y) : "f"(x));
    return y;
}
__device__ __forceinline__ void mma16816(float* d, const uint32_t* a, const uint32_t* b) {
    asm volatile(
        "mma.sync.aligned.m16n8k16.row.col.f32.f16.f16.f32 "
        "{%0,%1,%2,%3}, {%4,%5,%6,%7}, {%8,%9}, {%0,%1,%2,%3};"
        : "+f"(d[0]), "+f"(d[1]), "+f"(d[2]), "+f"(d[3])
        : "r"(a[0]), "r"(a[1]), "r"(a[2]), "r"(a[3]),
          "r"(b[0]), "r"(b[1]));
}
__device__ __forceinline__ void ldsm_x4(uint32_t* r, uint32_t addr) {
    asm volatile("ldmatrix.sync.aligned.m8n8.x4.shared.b16 {%0,%1,%2,%3}, [%4];"
        : "=r"(r[0]), "=r"(r[1]), "=r"(r[2]), "=r"(r[3]) : "r"(addr));
}
__device__ __forceinline__ void ldsm_x4_t(uint32_t* r, uint32_t addr) {
    asm volatile("ldmatrix.sync.aligned.m8n8.x4.trans.shared.b16 {%0,%1,%2,%3}, [%4];"
        : "=r"(r[0]), "=r"(r[1]), "=r"(r[2]), "=r"(r[3]) : "r"(addr));
}

// ---------------- fp16 cp.async 3-stage GEMM core (device function) ----------
// Block tile 64 x (NT*16), BK=32 halves, 128 threads, 4 warps, warp 32 x (NT*8).
// MODE 0: fp32 C (+bias). MODE 1: z=ctx@lk + zh addend + LSTM gates.
// MODE 2: fp16 C. Requires M%64==0, N%BN==0.
template<int MODE, int NT>
__device__ __forceinline__
void gemm_core(int bx, int by,
               const __half* __restrict__ A1, const __half* __restrict__ B1,
               const float* __restrict__ bias, float* __restrict__ C,
               int M, int N, int K, int lda, int ldb, int ldc,
               const __half* __restrict__ lk16, const float* __restrict__ lbP,
               const int* __restrict__ text, int step,
               const float* __restrict__ zhp)
{
    constexpr int BN = NT * 16;
    constexpr int PA = 40;
    constexpr int PB = BN + 8;
    constexpr int A_H = 64 * PA;
    constexpr int B_H = 32 * PB;
    constexpr int STAGE_BYTES = (A_H + B_H) * 2;
    constexpr int BCH = BN / 8;

    extern __shared__ __half SMh[];
    const int tid = threadIdx.x;
    const int wid = tid >> 5, lane = tid & 31;
    const int warpM = wid >> 1, warpN = wid & 1;
    const int g = lane >> 2, t = lane & 3;
    const int m0 = by * 64, n0 = bx * BN;
    const int nk = K / 32;
    const uint32_t sbase = (uint32_t)__cvta_generic_to_shared(SMh);

    const int lr8 = lane & 7;
    const int selR = (lane >> 3) & 1;
    const int selC = (lane >> 4) & 1;

    float acc[2][NT][4];
#pragma unroll
    for (int i = 0; i < 2; ++i)
#pragma unroll
        for (int j = 0; j < NT; ++j)
#pragma unroll
            for (int k = 0; k < 4; ++k) acc[i][j][k] = 0.f;

    auto issue = [&](int kt) {
        if (kt < nk) {
            const int k0 = kt * 32;
            const uint32_t ab = sbase + (uint32_t)(kt % 3) * STAGE_BYTES;
            const uint32_t bb = ab + A_H * 2;
#pragma unroll
            for (int i = 0; i < 2; ++i) {
                const int lin = tid + 128 * i;
                const int row = lin >> 2, q = lin & 3;
                const uint32_t d = ab + (uint32_t)(row * PA + q * 8) * 2u;
                const __half* s = A1 + (size_t)(m0 + row) * lda + k0 + q * 8;
                asm volatile("cp.async.cg.shared.global [%0], [%1], 16;"
                             :: "r"(d), "l"(s));
            }
#pragma unroll
            for (int i = 0; i < (32 * BCH) / 128; ++i) {
                const int lin = tid + 128 * i;
                const int kk = lin / BCH, q = lin % BCH;
                const uint32_t d = bb + (uint32_t)(kk * PB + q * 8) * 2u;
                const __half* s = B1 + (size_t)(k0 + kk) * ldb + n0 + q * 8;
                asm volatile("cp.async.cg.shared.global [%0], [%1], 16;"
                             :: "r"(d), "l"(s));
            }
        }
        asm volatile("cp.async.commit_group;" ::: "memory");
    };

    issue(0);
    issue(1);

    for (int kt = 0; kt < nk; ++kt) {
        asm volatile("cp.async.wait_group 1;" ::: "memory");
        __syncthreads();
        issue(kt + 2);

        const uint32_t ab = sbase + (uint32_t)(kt % 3) * STAGE_BYTES;
        const uint32_t bb = ab + A_H * 2;

        uint32_t fa[2][2][4], fb[2][NT][2];
        auto ldfrag = [&](int kb16, int slot) {
            const int kh = kb16 * 16;
#pragma unroll
            for (int mt = 0; mt < 2; ++mt) {
                const int row = warpM * 32 + mt * 16 + lr8 + selR * 8;
                const int col = kh + selC * 8;
                ldsm_x4(fa[slot][mt], ab + (uint32_t)(row * PA + col) * 2u);
            }
#pragma unroll
            for (int np = 0; np < NT / 2; ++np) {
                const int bk = kh + lr8 + selR * 8;
                const int bn = warpN * (NT * 8) + np * 16 + selC * 8;
                uint32_t q4[4];
                ldsm_x4_t(q4, bb + (uint32_t)(bk * PB + bn) * 2u);
                fb[slot][2 * np][0] = q4[0]; fb[slot][2 * np][1] = q4[1];
                fb[slot][2 * np + 1][0] = q4[2]; fb[slot][2 * np + 1][1] = q4[3];
            }
        };

        ldfrag(0, 0);
        ldfrag(1, 1);
#pragma unroll
        for (int s = 0; s < 2; ++s)
#pragma unroll
            for (int mt = 0; mt < 2; ++mt)
#pragma unroll
                for (int nt = 0; nt < NT; ++nt)
                    mma16816(acc[mt][nt], fa[s][mt], fb[s][nt]);
    }

    if (MODE == 0) {
#pragma unroll
        for (int mt = 0; mt < 2; ++mt) {
#pragma unroll
            for (int nt = 0; nt < NT; ++nt) {
                const int col = n0 + warpN * (NT * 8) + nt * 8 + 2 * t;
                const int row = m0 + warpM * 32 + mt * 16 + g;
                float b0 = bias ? bias[col] : 0.f;
                float b1 = bias ? bias[col + 1] : 0.f;
                *(float2*)(C + (size_t)row * ldc + col) =
                    make_float2(acc[mt][nt][0] + b0, acc[mt][nt][1] + b1);
                *(float2*)(C + (size_t)(row + 8) * ldc + col) =
                    make_float2(acc[mt][nt][2] + b0, acc[mt][nt][3] + b1);
            }
        }
    } else if (MODE == 2) {
        __half* C16 = (__half*)C;
#pragma unroll
        for (int mt = 0; mt < 2; ++mt) {
#pragma unroll
            for (int nt = 0; nt < NT; ++nt) {
                const int col = n0 + warpN * (NT * 8) + nt * 8 + 2 * t;
                const int row = m0 + warpM * 32 + mt * 16 + g;
                *(__half2*)(C16 + (size_t)row * ldc + col) =
                    __floats2half2_rn(acc[mt][nt][0], acc[mt][nt][1]);
                *(__half2*)(C16 + (size_t)(row + 8) * ldc + col) =
                    __floats2half2_rn(acc[mt][nt][2], acc[mt][nt][3]);
            }
        }
    } else {
        // fused LSTM gates; z = acc + zh + onehot + bias; C = fp16 h_out.
        __syncthreads();
        float* zs = (float*)SMh;
        constexpr int ZP = BN + 2;
#pragma unroll
        for (int mt = 0; mt < 2; ++mt) {
#pragma unroll
            for (int nt = 0; nt < NT; ++nt) {
                const int c0 = warpN * (NT * 8) + nt * 8 + 2 * t;
                const int r0 = warpM * 32 + mt * 16 + g;
                zs[r0 * ZP + c0]           = acc[mt][nt][0];
                zs[r0 * ZP + c0 + 1]       = acc[mt][nt][1];
                zs[(r0 + 8) * ZP + c0]     = acc[mt][nt][2];
                zs[(r0 + 8) * ZP + c0 + 1] = acc[mt][nt][3];
            }
        }
        __syncthreads();
        __half* hout = (__half*)C;
        const int j0 = n0 >> 2;
        constexpr int NJ = BN / 4;
#pragma unroll
        for (int p = tid; p < 64 * NJ; p += 128) {
            const int r = p & 63, jj = p >> 6;
            const int b = m0 + r, j = j0 + jj;
            const int ch = text[b * NS + step];
            const float* zrow = zs + r * ZP + jj * 4;
            const __half2* ohp =
                (const __half2*)(lk16 + (size_t)(CC + ch) * (4 * HH) + 4 * j);
            float2 o01 = __half22float2(ohp[0]);
            float2 o23 = __half22float2(ohp[1]);
            float4 bb4 = *(const float4*)(lbP + 4 * j);
            float4 zh4 = *(const float4*)(zhp + (size_t)b * (4 * HH) + 4 * j);
            float zi = zrow[0] + zh4.x + o01.x + bb4.x;
            float zf = zrow[1] + zh4.y + o01.y + bb4.y;
            float zg = zrow[2] + zh4.z + o23.x + bb4.z;
            float zo = zrow[3] + zh4.w + o23.y + bb4.w;
            const int ci = b * HH + j;
            float cn = sigm(zf) * g_c[ci] + sigm(zi) * tanhf(zg);
            float hn = sigm(zo) * tanhf(cn);
            __half hh = __float2half_rn(hn);
            g_c[ci] = cn;
            hout[ci] = hh;
            g_hs16[((size_t)b * NS + step) * HH + j] = hh;
        }
    }
}

// generic GEMM kernel wrapper
template<int MODE, int NT>
__global__ __launch_bounds__(128)
void gemm_h(const __half* __restrict__ A1, const __half* __restrict__ B1,
            const float* __restrict__ bias, float* __restrict__ C,
            int M, int N, int K, int lda, int ldb, int ldc,
            const __half* __restrict__ lk16, const float* __restrict__ lbP,
            const int* __restrict__ text, int step,
            const float* __restrict__ zhp)
{
    gemm_core<MODE, NT>(blockIdx.x, blockIdx.y, A1, B1, bias, C,
                        M, N, K, lda, ldb, ldc, lk16, lbP, text, step, zhp);
}

// ---------------- attention body (128 threads, tanh.approx) ------------------
__device__ __forceinline__
void attn_body(int b,
               const float* __restrict__ q, const float* __restrict__ bh,
               const __half* __restrict__ hp16, const __half* __restrict__ bh16,
               const float* __restrict__ Ws, __half* __restrict__ ctx16)
{
    extern __shared__ __half SMh[];
    float* qs = (float*)SMh;          // [512]
    float* ws = qs + HH;              // [512]
    float* e  = ws + HH;              // [64]

    const int tid = threadIdx.x;
    for (int i = tid; i < HH; i += 128) {
        qs[i] = q[(size_t)b * HH + i] + bh[i];
        ws[i] = Ws[i];
    }
    __syncthreads();

    const int warp = tid >> 5, lane = tid & 31;
    for (int t = warp; t < TT; t += 4) {
        const __half2* __restrict__ hp =
            (const __half2*)(hp16 + ((size_t)b * TT + t) * HH);
        float p = 0.f;
#pragma unroll
        for (int j = 0; j < 8; ++j) {
            const int idx = lane + 32 * j;
            float2 f = __half22float2(hp[idx]);
            float2 qv = *(const float2*)&qs[2 * idx];
            float2 wv = *(const float2*)&ws[2 * idx];
            p += tanha(f.x + qv.x) * wv.x + tanha(f.y + qv.y) * wv.y;
        }
#pragma unroll
        for (int o = 16; o; o >>= 1) p += __shfl_xor_sync(0xffffffffu, p, o);
        if (lane == 0) e[t] = p;
    }
    __syncthreads();

    if (warp == 0) {
        float v0 = e[lane], v1 = e[lane + 32];
        float m = fmaxf(v0, v1);
#pragma unroll
        for (int o = 16; o; o >>= 1) m = fmaxf(m, __shfl_xor_sync(0xffffffffu, m, o));
        float x0 = __expf(v0 - m), x1 = __expf(v1 - m);
        float s = x0 + x1;
#pragma unroll
        for (int o = 16; o; o >>= 1) s += __shfl_xor_sync(0xffffffffu, s, o);
        float inv = 1.f / s;
        e[lane] = x0 * inv;
        e[lane + 32] = x1 * inv;
    }
    __syncthreads();

    {
        const __half2* __restrict__ bp =
            (const __half2*)(bh16 + (size_t)b * TT * CC);
#pragma unroll
        for (int cc = tid; cc < CC / 2; cc += 128) {
            float2 acc = make_float2(0.f, 0.f);
#pragma unroll 8
            for (int t = 0; t < TT; ++t) {
                float2 f = __half22float2(bp[t * (CC / 2) + cc]);
                float a = e[t];
                acc.x = fmaf(a, f.x, acc.x);
                acc.y = fmaf(a, f.y, acc.y);
            }
            ((__half2*)ctx16)[(size_t)b * (CC / 2) + cc] =
                __floats2half2_rn(acc.x, acc.y);
        }
    }
}

// ---------------- combined [zh GEMM || attention] kernel ---------------------
// Blocks 0..255: zh = h @ lr16 (M=512, N=2048, BN=64 -> 32x8 tiles)
// Blocks 256..767: attention for batch row (blk - 256)
__global__ __launch_bounds__(128)
void attn_zh_kernel(const __half* __restrict__ hin,
                    const __half* __restrict__ lr16,
                    float* __restrict__ zh,
                    const float* __restrict__ q, const float* __restrict__ bh,
                    const __half* __restrict__ hp16,
                    const __half* __restrict__ bh16,
                    const float* __restrict__ Ws,
                    __half* __restrict__ ctx16)
{
    const int blk = blockIdx.x;
    if (blk < 256) {
        gemm_core<0, 4>(blk & 31, blk >> 5, hin, lr16, nullptr, zh,
                        BB, 4 * HH, HH, HH, 4 * HH, 4 * HH,
                        nullptr, nullptr, nullptr, 0, nullptr);
    } else {
        attn_body(blk - 256, q, bh, hp16, bh16, Ws, ctx16);
    }
}

// ---------------- prep kernels ------------------------------------------------
__global__ __launch_bounds__(256)
void permute_gates_h(const float* __restrict__ in, __half* __restrict__ out, int total)
{
    int idx = blockIdx.x * 256 + threadIdx.x;
    if (idx >= total) return;
    int row = idx >> 11, oc = idx & 2047;
    int j = oc >> 2, gate = oc & 3;
    out[idx] = __float2half_rn(in[(size_t)row * 2048 + gate * HH + j]);
}
__global__ __launch_bounds__(256)
void permute_bias(const float* __restrict__ in, float* __restrict__ out)
{
    int idx = blockIdx.x * 256 + threadIdx.x;
    if (idx >= 4 * HH) return;
    int j = idx >> 2, gate = idx & 3;
    out[idx] = in[gate * HH + j];
}
__global__ __launch_bounds__(256)
void half_copy(const float* __restrict__ in, __half* __restrict__ out, int n4)
{
    int i = blockIdx.x * 256 + threadIdx.x;
    if (i >= n4) return;
    float4 v = ((const float4*)in)[i];
    ((__half2*)out)[2 * i]     = __floats2half2_rn(v.x, v.y);
    ((__half2*)out)[2 * i + 1] = __floats2half2_rn(v.z, v.w);
}

// ---------------- launch -----------------------------------------------------
extern "C" void kernel_launch(void* const* d_in, const int* in_sizes, int n_in,
                              void* d_out, int out_size)
{
    int off = 0;
    if (n_in >= 3 && in_sizes[2] == 1) off = 1;
    const float* batch_H = (const float*)d_in[0];
    const int*   text    = (const int*)  d_in[1];
    const float* Wi      = (const float*)d_in[2 + off];
    const float* Wh      = (const float*)d_in[3 + off];
    const float* bh      = (const float*)d_in[4 + off];
    const float* Ws      = (const float*)d_in[5 + off];
    const float* lk      = (const float*)d_in[6 + off];
    const float* lr      = (const float*)d_in[7 + off];
    const float* lb      = (const float*)d_in[8 + off];
    const float* Wgen    = (const float*)d_in[9 + off];
    const float* bgen    = (const float*)d_in[10 + off];

    __half *hp16, *bh16, *wi16, *wg16, *wh16, *lr16, *lk16, *hA, *hB, *ctx16, *hs16;
    float *lbP, *q, *zh, *c;
    cudaGetSymbolAddress((void**)&hp16, g_hp16);
    cudaGetSymbolAddress((void**)&bh16, g_bh16);
    cudaGetSymbolAddress((void**)&wi16, g_wi16);
    cudaGetSymbolAddress((void**)&wg16, g_wg16);
    cudaGetSymbolAddress((void**)&wh16, g_wh16);
    cudaGetSymbolAddress((void**)&lr16, g_lr16);
    cudaGetSymbolAddress((void**)&lk16, g_lk16);
    cudaGetSymbolAddress((void**)&lbP,  g_lbP);
    cudaGetSymbolAddress((void**)&q,    g_q);
    cudaGetSymbolAddress((void**)&zh,   g_zh);
    cudaGetSymbolAddress((void**)&hA,   g_h16A);
    cudaGetSymbolAddress((void**)&hB,   g_h16B);
    cudaGetSymbolAddress((void**)&ctx16,g_ctx16);
    cudaGetSymbolAddress((void**)&hs16, g_hs16);
    cudaGetSymbolAddress((void**)&c,    g_c);

    static bool attr_done = false;
    if (!attr_done) {
        cudaFuncSetAttribute(gemm_h<0,2>, cudaFuncAttributeMaxDynamicSharedMemorySize, 23040);
        cudaFuncSetAttribute(gemm_h<1,4>, cudaFuncAttributeMaxDynamicSharedMemorySize, 29184);
        cudaFuncSetAttribute(gemm_h<2,8>, cudaFuncAttributeMaxDynamicSharedMemorySize, 41472);
        cudaFuncSetAttribute(attn_zh_kernel, cudaFuncAttributeMaxDynamicSharedMemorySize, 29184);
        attr_done = true;
    }

    cudaMemsetAsync(hA, 0, (size_t)BB * HH * sizeof(__half));
    cudaMemsetAsync(c,  0, (size_t)BB * HH * sizeof(float));

    // prep
    half_copy<<<(BB * TT * CC / 4 + 255) / 256, 256>>>(batch_H, bh16, BB * TT * CC / 4);
    half_copy<<<(CC * HH / 4 + 255) / 256, 256>>>(Wi, wi16, CC * HH / 4);
    half_copy<<<(HH * HH / 4 + 255) / 256, 256>>>(Wh, wh16, HH * HH / 4);
    half_copy<<<(HH * NCLS / 4 + 255) / 256, 256>>>(Wgen, wg16, HH * NCLS / 4);
    permute_gates_h<<<((CC + NCLS) * 4 * HH + 255) / 256, 256>>>(lk, lk16, (CC + NCLS) * 4 * HH);
    permute_gates_h<<<(HH * 4 * HH + 255) / 256, 256>>>(lr, lr16, HH * 4 * HH);
    permute_bias<<<(4 * HH + 255) / 256, 256>>>(lb, lbP);

    // Hproj(fp16) = bh16 [B*T, C] @ wi16 [C, H]   (BN=128, grid 2048)
    gemm_h<2,8><<<dim3(HH / 128, (BB * TT) / 64), 128, 41472>>>(
        bh16, wi16, nullptr, (float*)hp16,
        BB * TT, HH, CC, CC, HH, HH, nullptr, nullptr, nullptr, 0, nullptr);

    __half* hbuf[2] = { hA, hB };
    for (int s = 0; s < NS; ++s) {
        __half* hin  = hbuf[s & 1];
        __half* hout = hbuf[(s + 1) & 1];

        // q = h @ wh16 (N=512, BN=32, grid 128; bh added in attn)
        gemm_h<0,2><<<dim3(HH / 32, BB / 64), 128, 23040>>>(
            hin, wh16, nullptr, q,
            BB, HH, HH, HH, HH, HH, nullptr, nullptr, nullptr, 0, nullptr);

        // combined: blocks 0-255 zh = h@lr ; blocks 256-767 attention
        attn_zh_kernel<<<768, 128, 29184>>>(
            hin, lr16, zh, q, bh, hp16, bh16, Ws, ctx16);

        // fused: z = ctx @ lk16 + zh + gates  (BN=64, grid 256)
        gemm_h<1,4><<<dim3((4 * HH) / 64, BB / 64), 128, 29184>>>(
            ctx16, lk16, nullptr, (float*)hout,
            BB, 4 * HH, CC, CC, 4 * HH, 4 * HH, lk16, lbP, text, s, zh);
    }

    // probs = hs16 [B*NS, H] @ wg16 [H, NC] + bgen  (BN=32, grid 624, fp32 out)
    gemm_h<0,2><<<dim3(NCLS / 32, (BB * NS) / 64), 128, 23040>>>(
        hs16, wg16, bgen, (float*)d_out,
        BB * NS, NCLS, HH, HH, NCLS, NCLS, nullptr, nullptr, nullptr, 0, nullptr);
}